// round 6
// baseline (speedup 1.0000x reference)
#include <cuda_runtime.h>
#include <cuda_fp16.h>
#include <cstdint>
#include <math.h>

// Problem constants
#define B_    2
#define S_    2048
#define HID_  4096
#define NH_   32
#define NKV_  8
#define HD_   128
#define MTOK  (B_ * S_)                    // 4096
#define NQKV  (NH_ * HD_ + 2 * NKV_ * HD_) // 6144
#define SCALING 0.08838834764831845f
#define LOG2E  1.4426950408889634f

// fp32 scratch (QKV projection output, pre-rope)
__device__ float g_Q[B_ * NH_ * S_ * HD_];
__device__ float g_K[B_ * NKV_ * S_ * HD_];
__device__ float g_V[B_ * NKV_ * S_ * HD_];

// split-fp16 post-rope QKV for attention
__device__ __half g_Qh[B_ * NH_ * S_ * HD_];
__device__ __half g_Ql[B_ * NH_ * S_ * HD_];
__device__ __half g_Kh[B_ * NKV_ * S_ * HD_];
__device__ __half g_Kl[B_ * NKV_ * S_ * HD_];
__device__ __half g_Vh[B_ * NKV_ * S_ * HD_];
__device__ __half g_Vl[B_ * NKV_ * S_ * HD_];

// fp16 split scratch for projections
__device__ __half g_Ahi[MTOK * HID_];
__device__ __half g_Alo[MTOK * HID_];
__device__ __half g_Whi[NQKV * HID_];
__device__ __half g_Wlo[NQKV * HID_];
__device__ __half g_WOhi[HID_ * HID_];
__device__ __half g_WOlo[HID_ * HID_];
__device__ __half g_Ohi[MTOK * HID_];
__device__ __half g_Olo[MTOK * HID_];

// ---------------------------------------------------------------------------
__global__ __launch_bounds__(256) void split_kernel(
    const float* __restrict__ src, __half* __restrict__ hi,
    __half* __restrict__ lo, int n4)
{
    int i = blockIdx.x * 256 + threadIdx.x;
    if (i >= n4) return;
    float4 v = ((const float4*)src)[i];
    __half h0 = __float2half_rn(v.x);
    __half h1 = __float2half_rn(v.y);
    __half h2 = __float2half_rn(v.z);
    __half h3 = __float2half_rn(v.w);
    __half l0 = __float2half_rn(v.x - __half2float(h0));
    __half l1 = __float2half_rn(v.y - __half2float(h1));
    __half l2 = __float2half_rn(v.z - __half2float(h2));
    __half l3 = __float2half_rn(v.w - __half2float(h3));
    ((__half2*)hi)[2 * i + 0] = __halves2half2(h0, h1);
    ((__half2*)hi)[2 * i + 1] = __halves2half2(h2, h3);
    ((__half2*)lo)[2 * i + 0] = __halves2half2(l0, l1);
    ((__half2*)lo)[2 * i + 1] = __halves2half2(l2, l3);
}

// ---------------------------------------------------------------------------
// Split-fp16 tensor-core GEMM: C[M,N] = A[M,K] @ B[N,K]^T  (fp32 result)
// 256x128x32 block tile, 256 threads (8 warps as 4(M) x 2(N)), warp tile 64x64.
// 3-stage cp.async pipeline. 3 mma passes: AhBh + AhBl + AlBh.
// MODE 0: plain store; MODE 1: QKV scatter into g_Q/g_K/g_V.
// ---------------------------------------------------------------------------
#define BM2 256
#define BN2 128
#define BKc 32
#define SSTRIDE 40
#define A_TB (256 * SSTRIDE * 2)        // 20480 bytes per A array
#define B_TB (128 * SSTRIDE * 2)        // 10240 bytes per B array
#define OFF_AH 0
#define OFF_AL A_TB
#define OFF_BH (2 * A_TB)
#define OFF_BL (2 * A_TB + B_TB)
#define STG2 (2 * A_TB + 2 * B_TB)      // 61440 per stage
#define NSTG 3
#define HGEMM_SMEM (NSTG * STG2)        // 184320 bytes

#define LDMX4(R0, R1, R2, R3, ADDR)                                          \
    asm volatile("ldmatrix.sync.aligned.m8n8.x4.shared.b16 {%0,%1,%2,%3}, [%4];" \
                 : "=r"(R0), "=r"(R1), "=r"(R2), "=r"(R3) : "r"(ADDR))

#define LDMX4T(R0, R1, R2, R3, ADDR)                                         \
    asm volatile("ldmatrix.sync.aligned.m8n8.x4.trans.shared.b16 {%0,%1,%2,%3}, [%4];" \
                 : "=r"(R0), "=r"(R1), "=r"(R2), "=r"(R3) : "r"(ADDR))

#define MMA16816(C, A, B0, B1)                                               \
    asm volatile("mma.sync.aligned.m16n8k16.row.col.f32.f16.f16.f32 "        \
                 "{%0,%1,%2,%3}, {%4,%5,%6,%7}, {%8,%9}, {%0,%1,%2,%3};"     \
                 : "+f"(C[0]), "+f"(C[1]), "+f"(C[2]), "+f"(C[3])            \
                 : "r"(A[0]), "r"(A[1]), "r"(A[2]), "r"(A[3]), "r"(B0), "r"(B1))

template <int MODE>
__global__ __launch_bounds__(256, 1) void hgemm(
    const __half* __restrict__ Ah, const __half* __restrict__ Al,
    const __half* __restrict__ Bh, const __half* __restrict__ Bl,
    float* __restrict__ C, int M, int N, int K)
{
    extern __shared__ __half smh[];
    const unsigned smem_base = (unsigned)__cvta_generic_to_shared(smh);

    const int tid = threadIdx.x;
    const int lane = tid & 31;
    const int wid = tid >> 5;
    const int wm = wid & 3;     // 0..3 (M)
    const int wn = wid >> 2;    // 0..1 (N)
    const int m0 = blockIdx.y * BM2;
    const int n0 = blockIdx.x * BN2;

    const __half* gAh = Ah + (long)m0 * K;
    const __half* gAl = Al + (long)m0 * K;
    const __half* gBh = Bh + (long)n0 * K;
    const __half* gBl = Bl + (long)n0 * K;

    const int r0 = tid >> 2;        // 0..63
    const int c0 = tid & 3;         // 16B chunk (8 halves)

    auto load_stage = [&](int stage, int k0) {
        unsigned sb = smem_base + stage * STG2;
#pragma unroll
        for (int t = 0; t < 4; t++) {
            int row = r0 + t * 64;
            unsigned ro = (row * SSTRIDE + c0 * 8) * 2;
            const __half* ga = gAh + (long)row * K + k0 + c0 * 8;
            const __half* gl = gAl + (long)row * K + k0 + c0 * 8;
            asm volatile("cp.async.ca.shared.global [%0], [%1], 16;"
                         :: "r"(sb + OFF_AH + ro), "l"(ga));
            asm volatile("cp.async.ca.shared.global [%0], [%1], 16;"
                         :: "r"(sb + OFF_AL + ro), "l"(gl));
        }
#pragma unroll
        for (int t = 0; t < 2; t++) {
            int row = r0 + t * 64;
            unsigned ro = (row * SSTRIDE + c0 * 8) * 2;
            const __half* gb = gBh + (long)row * K + k0 + c0 * 8;
            const __half* gc = gBl + (long)row * K + k0 + c0 * 8;
            asm volatile("cp.async.ca.shared.global [%0], [%1], 16;"
                         :: "r"(sb + OFF_BH + ro), "l"(gb));
            asm volatile("cp.async.ca.shared.global [%0], [%1], 16;"
                         :: "r"(sb + OFF_BL + ro), "l"(gc));
        }
    };

    float acc[4][8][4];
#pragma unroll
    for (int i = 0; i < 4; i++)
#pragma unroll
        for (int j = 0; j < 8; j++)
#pragma unroll
            for (int r = 0; r < 4; r++) acc[i][j][r] = 0.f;

    const int nk = K / BKc;
    load_stage(0, 0);
    asm volatile("cp.async.commit_group;");
    load_stage(1, BKc);
    asm volatile("cp.async.commit_group;");
    load_stage(2, 2 * BKc);
    asm volatile("cp.async.commit_group;");

    int stage = 0;
    for (int kc = 0; kc < nk; kc++) {
        asm volatile("cp.async.wait_group 2;");
        __syncthreads();

        unsigned sb = smem_base + stage * STG2;

#pragma unroll
        for (int ks = 0; ks < 2; ks++) {
            const int kcol = ks * 16 + (lane >> 4) * 8;
            // B fragments: 8 nj tiles (hi+lo)
            uint32_t bfh[8][2], bfl[8][2];
#pragma unroll
            for (int p = 0; p < 4; p++) {
                unsigned off = ((wn * 64 + p * 16 + (lane & 15)) * SSTRIDE + kcol) * 2;
                uint32_t t0, t1, t2, t3;
                LDMX4(t0, t1, t2, t3, sb + OFF_BH + off);
                bfh[2 * p][0] = t0; bfh[2 * p][1] = t2;
                bfh[2 * p + 1][0] = t1; bfh[2 * p + 1][1] = t3;
                LDMX4(t0, t1, t2, t3, sb + OFF_BL + off);
                bfl[2 * p][0] = t0; bfl[2 * p][1] = t2;
                bfl[2 * p + 1][0] = t1; bfl[2 * p + 1][1] = t3;
            }
#pragma unroll
            for (int mi = 0; mi < 4; mi++) {
                unsigned aoff = ((wm * 64 + mi * 16 + (lane & 15)) * SSTRIDE + kcol) * 2;
                uint32_t ah[4], al[4];
                LDMX4(ah[0], ah[1], ah[2], ah[3], sb + OFF_AH + aoff);
                LDMX4(al[0], al[1], al[2], al[3], sb + OFF_AL + aoff);
#pragma unroll
                for (int nj = 0; nj < 8; nj++) {
                    MMA16816(acc[mi][nj], ah, bfh[nj][0], bfh[nj][1]);
                    MMA16816(acc[mi][nj], ah, bfl[nj][0], bfl[nj][1]);
                    MMA16816(acc[mi][nj], al, bfh[nj][0], bfh[nj][1]);
                }
            }
        }
        __syncthreads();
        int knext = (kc + NSTG) * BKc;
        if (knext < K) load_stage(stage, knext);
        asm volatile("cp.async.commit_group;");
        stage = (stage == NSTG - 1) ? 0 : stage + 1;
    }

    // Epilogue
    const int lr = lane >> 2;
    const int lc = (lane & 3) * 2;
#pragma unroll
    for (int mi = 0; mi < 4; mi++) {
#pragma unroll
        for (int hf = 0; hf < 2; hf++) {
            int row = m0 + wm * 64 + mi * 16 + hf * 8 + lr;
            float* dst;
            if (MODE == 0) {
                dst = C + (long)row * N + n0;
            } else {
                int b = row >> 11;
                int s = row & 2047;
                if (n0 < NH_ * HD_) {
                    int h = n0 >> 7;
                    dst = g_Q + (((long)(b * NH_ + h) * S_ + s) << 7);
                } else if (n0 < NH_ * HD_ + NKV_ * HD_) {
                    int h = (n0 - NH_ * HD_) >> 7;
                    dst = g_K + (((long)(b * NKV_ + h) * S_ + s) << 7);
                } else {
                    int h = (n0 - NH_ * HD_ - NKV_ * HD_) >> 7;
                    dst = g_V + (((long)(b * NKV_ + h) * S_ + s) << 7);
                }
            }
#pragma unroll
            for (int nj = 0; nj < 8; nj++) {
                int col = wn * 64 + nj * 8 + lc;
                float2 v = make_float2(acc[mi][nj][hf * 2 + 0],
                                       acc[mi][nj][hf * 2 + 1]);
                *(float2*)(dst + col) = v;
            }
        }
    }
}

// ---------------------------------------------------------------------------
// RoPE + split-fp16 convert
// ---------------------------------------------------------------------------
#define QPAIRS (B_ * NH_ * S_ * 64)
#define KPAIRS (B_ * NKV_ * S_ * 64)

__device__ __forceinline__ void split2w(float v, __half* ph, __half* pl, long off)
{
    __half h = __float2half_rn(v);
    ph[off] = h;
    pl[off] = __float2half_rn(v - __half2float(h));
}

__global__ __launch_bounds__(256) void rope_conv_kernel(
    const float* __restrict__ cosb, const float* __restrict__ sinb)
{
    int idx = blockIdx.x * 256 + threadIdx.x;
    if (idx < QPAIRS) {
        int d = idx & 63;
        int s = (idx >> 6) & 2047;
        int h = (idx >> 17) & 31;
        int b = idx >> 22;
        long base = ((long)(b * NH_ + h) * S_ + s) << 7;
        float c  = cosb[((long)(b * S_ + s) << 7) + d];
        float sn = sinb[((long)(b * S_ + s) << 7) + d];
        float x1 = g_Q[base + d];
        float x2 = g_Q[base + d + 64];
        split2w(x1 * c - x2 * sn, g_Qh, g_Ql, base + d);
        split2w(x2 * c + x1 * sn, g_Qh, g_Ql, base + d + 64);
    } else if (idx < QPAIRS + KPAIRS) {
        int i2 = idx - QPAIRS;
        int d = i2 & 63;
        int s = (i2 >> 6) & 2047;
        int h = (i2 >> 17) & 7;
        int b = i2 >> 20;
        long base = ((long)(b * NKV_ + h) * S_ + s) << 7;
        float c  = cosb[((long)(b * S_ + s) << 7) + d];
        float sn = sinb[((long)(b * S_ + s) << 7) + d];
        float x1 = g_K[base + d];
        float x2 = g_K[base + d + 64];
        split2w(x1 * c - x2 * sn, g_Kh, g_Kl, base + d);
        split2w(x2 * c + x1 * sn, g_Kh, g_Kl, base + d + 64);
    } else if (idx < QPAIRS + 2 * KPAIRS) {
        int i3 = idx - QPAIRS - KPAIRS;
        int d = i3 & 63;
        int s = (i3 >> 6) & 2047;
        int h = (i3 >> 17) & 7;
        int b = i3 >> 20;
        long base = ((long)(b * NKV_ + h) * S_ + s) << 7;
        split2w(g_V[base + d],      g_Vh, g_Vl, base + d);
        split2w(g_V[base + d + 64], g_Vh, g_Vl, base + d + 64);
    }
}

// ---------------------------------------------------------------------------
// FFMA-only exp2 (no MUFU). x <= 0 expected; rel err ~2e-5.
// ---------------------------------------------------------------------------
__device__ __forceinline__ float exp2p(float x)
{
    x = fmaxf(x, -120.f);
    float fl = floorf(x);
    float f = x - fl;
    float p = 1.5403530393381606e-4f;
    p = fmaf(p, f, 1.3333558146428443e-3f);
    p = fmaf(p, f, 9.6181291076284770e-3f);
    p = fmaf(p, f, 5.5504108664821580e-2f);
    p = fmaf(p, f, 2.4022650695910070e-1f);
    p = fmaf(p, f, 6.9314718055994531e-1f);
    p = fmaf(p, f, 1.0f);
    return __int_as_float(__float_as_int(p) + (((int)fl) << 23));
}

// ---------------------------------------------------------------------------
// Tensor-core causal flash attention (unchanged from R4).
// ---------------------------------------------------------------------------
#define ASTR 136
#define QH_B  0
#define QL_B  (128 * ASTR * 2)
#define STG_B (2 * 128 * ASTR * 2)
#define AKH_B 0
#define AKL_B (64 * ASTR * 2)
#define AVH_B (2 * 64 * ASTR * 2)
#define AVL_B (3 * 64 * ASTR * 2)
#define STG_SZB (4 * 64 * ASTR * 2)
#define ATT_SMEM (STG_B + 2 * STG_SZB)

__global__ __launch_bounds__(256, 1) void attn_mma_kernel()
{
    extern __shared__ __half sm[];
    const unsigned sbase = (unsigned)__cvta_generic_to_shared(sm);
    const int tid = threadIdx.x;
    const int lane = tid & 31;
    const int w = tid >> 5;
    const int qt = gridDim.x - 1 - blockIdx.x;
    const int bh = blockIdx.y;
    const int b = bh >> 5;
    const int h = bh & 31;
    const int hk = h >> 2;

    const __half* Qhp = g_Qh + ((long)(b * NH_ + h) * S_ << 7);
    const __half* Qlp = g_Ql + ((long)(b * NH_ + h) * S_ << 7);
    const __half* Khp = g_Kh + ((long)(b * NKV_ + hk) * S_ << 7);
    const __half* Klp = g_Kl + ((long)(b * NKV_ + hk) * S_ << 7);
    const __half* Vhp = g_Vh + ((long)(b * NKV_ + hk) * S_ << 7);
    const __half* Vlp = g_Vl + ((long)(b * NKV_ + hk) * S_ << 7);

    const int ktmax = 2 * qt + 1;
    const int rr = tid >> 4;
    const int cc = (tid & 15) * 8;

    auto cpa = [&](unsigned sboff, const __half* g) {
        asm volatile("cp.async.ca.shared.global [%0], [%1], 16;"
                     :: "r"(sbase + sboff), "l"(g));
    };
    auto load_kv = [&](int kt) {
        unsigned st = STG_B + (kt & 1) * STG_SZB;
        const __half* kb = Khp + (long)kt * 64 * 128;
        const __half* lb = Klp + (long)kt * 64 * 128;
        const __half* vb = Vhp + (long)kt * 64 * 128;
        const __half* wb = Vlp + (long)kt * 64 * 128;
#pragma unroll
        for (int it = 0; it < 4; it++) {
            int row = rr + it * 16;
            unsigned ro = (row * ASTR) * 2 + cc * 2;
            cpa(st + AKH_B + ro, kb + row * 128 + cc);
            cpa(st + AKL_B + ro, lb + row * 128 + cc);
            cpa(st + AVH_B + ro, vb + row * 128 + cc);
            cpa(st + AVL_B + ro, wb + row * 128 + cc);
        }
    };

    {
#pragma unroll
        for (int it = 0; it < 8; it++) {
            int row = rr + it * 16;
            unsigned ro = (row * ASTR) * 2 + cc * 2;
            cpa(QH_B + ro, Qhp + (long)(qt * 128 + row) * 128 + cc);
            cpa(QL_B + ro, Qlp + (long)(qt * 128 + row) * 128 + cc);
        }
        load_kv(0);
    }
    asm volatile("cp.async.commit_group;");
    load_kv(1);
    asm volatile("cp.async.commit_group;");

    float oacc[16][4];
#pragma unroll
    for (int t = 0; t < 16; t++)
#pragma unroll
        for (int e = 0; e < 4; e++) oacc[t][e] = 0.f;
    float mrow[2] = {-1e30f, -1e30f};
    float lrow[2] = {0.f, 0.f};

    const int qrow0 = qt * 128 + w * 16 + (lane >> 2);
    const float SL = SCALING * LOG2E;

    for (int kt = 0; kt <= ktmax; kt++) {
        asm volatile("cp.async.wait_group 1;");
        __syncthreads();

        unsigned st = sbase + STG_B + (kt & 1) * STG_SZB;

        float sacc[8][4];
#pragma unroll
        for (int j = 0; j < 8; j++)
#pragma unroll
            for (int e = 0; e < 4; e++) sacc[j][e] = 0.f;

#pragma unroll
        for (int ks = 0; ks < 8; ks++) {
            const int kcol = ks * 16 + (lane >> 4) * 8;
            unsigned aoff = ((w * 16 + (lane & 15)) * ASTR + kcol) * 2;
            uint32_t ah[4], al[4];
            LDMX4(ah[0], ah[1], ah[2], ah[3], sbase + QH_B + aoff);
            LDMX4(al[0], al[1], al[2], al[3], sbase + QL_B + aoff);
#pragma unroll
            for (int p = 0; p < 4; p++) {
                unsigned boff = ((p * 16 + (lane & 15)) * ASTR + kcol) * 2;
                uint32_t t0, t1, t2, t3, u0, u1, u2, u3;
                LDMX4(t0, t1, t2, t3, st + AKH_B + boff);
                LDMX4(u0, u1, u2, u3, st + AKL_B + boff);
                MMA16816(sacc[2 * p],     ah, t0, t2);
                MMA16816(sacc[2 * p],     al, t0, t2);
                MMA16816(sacc[2 * p],     ah, u0, u2);
                MMA16816(sacc[2 * p + 1], ah, t1, t3);
                MMA16816(sacc[2 * p + 1], al, t1, t3);
                MMA16816(sacc[2 * p + 1], ah, u1, u3);
            }
        }

        const bool diag = (kt >= 2 * qt);
        float rmax[2] = {-1e30f, -1e30f};
#pragma unroll
        for (int j = 0; j < 8; j++)
#pragma unroll
            for (int e = 0; e < 4; e++) {
                float v = sacc[j][e] * SL;
                if (diag) {
                    int col = kt * 64 + j * 8 + (lane & 3) * 2 + (e & 1);
                    int row = qrow0 + (e >> 1) * 8;
                    if (col > row) v = -1e30f;
                }
                sacc[j][e] = v;
                rmax[e >> 1] = fmaxf(rmax[e >> 1], v);
            }
#pragma unroll
        for (int r = 0; r < 2; r++) {
            rmax[r] = fmaxf(rmax[r], __shfl_xor_sync(0xffffffffu, rmax[r], 1));
            rmax[r] = fmaxf(rmax[r], __shfl_xor_sync(0xffffffffu, rmax[r], 2));
        }
        float mn0 = fmaxf(mrow[0], rmax[0]);
        float mn1 = fmaxf(mrow[1], rmax[1]);
        float al0 = exp2p(mrow[0] - mn0);
        float al1 = exp2p(mrow[1] - mn1);
        mrow[0] = mn0; mrow[1] = mn1;

        uint32_t ph[8][2], pl[8][2];
        float ls0 = 0.f, ls1 = 0.f;
#pragma unroll
        for (int j = 0; j < 8; j++) {
            float p0 = exp2p(sacc[j][0] - mn0);
            float p1 = exp2p(sacc[j][1] - mn0);
            float p2 = exp2p(sacc[j][2] - mn1);
            float p3 = exp2p(sacc[j][3] - mn1);
            ls0 += p0 + p1;
            ls1 += p2 + p3;
            __half2 h01 = __floats2half2_rn(p0, p1);
            __half2 h23 = __floats2half2_rn(p2, p3);
            ph[j][0] = *(uint32_t*)&h01;
            ph[j][1] = *(uint32_t*)&h23;
            float2 f01 = __half22float2(h01);
            float2 f23 = __half22float2(h23);
            __half2 l01 = __floats2half2_rn(p0 - f01.x, p1 - f01.y);
            __half2 l23 = __floats2half2_rn(p2 - f23.x, p3 - f23.y);
            pl[j][0] = *(uint32_t*)&l01;
            pl[j][1] = *(uint32_t*)&l23;
        }
        ls0 += __shfl_xor_sync(0xffffffffu, ls0, 1);
        ls0 += __shfl_xor_sync(0xffffffffu, ls0, 2);
        ls1 += __shfl_xor_sync(0xffffffffu, ls1, 1);
        ls1 += __shfl_xor_sync(0xffffffffu, ls1, 2);
        lrow[0] = lrow[0] * al0 + ls0;
        lrow[1] = lrow[1] * al1 + ls1;
#pragma unroll
        for (int t = 0; t < 16; t++) {
            oacc[t][0] *= al0; oacc[t][1] *= al0;
            oacc[t][2] *= al1; oacc[t][3] *= al1;
        }

#pragma unroll
        for (int dk = 0; dk < 4; dk++) {
            uint32_t aPh[4] = {ph[2 * dk][0], ph[2 * dk][1],
                               ph[2 * dk + 1][0], ph[2 * dk + 1][1]};
            uint32_t aPl[4] = {pl[2 * dk][0], pl[2 * dk][1],
                               pl[2 * dk + 1][0], pl[2 * dk + 1][1]};
#pragma unroll
            for (int np = 0; np < 8; np++) {
                unsigned vo = ((dk * 16 + (lane & 15)) * ASTR +
                               np * 16 + (lane >> 4) * 8) * 2;
                uint32_t t0, t1, t2, t3, u0, u1, u2, u3;
                LDMX4T(t0, t1, t2, t3, st + AVH_B + vo);
                LDMX4T(u0, u1, u2, u3, st + AVL_B + vo);
                MMA16816(oacc[2 * np],     aPh, t0, t1);
                MMA16816(oacc[2 * np],     aPh, u0, u1);
                MMA16816(oacc[2 * np],     aPl, t0, t1);
                MMA16816(oacc[2 * np + 1], aPh, t2, t3);
                MMA16816(oacc[2 * np + 1], aPh, u2, u3);
                MMA16816(oacc[2 * np + 1], aPl, t2, t3);
            }
        }

        __syncthreads();
        if (kt + 2 <= ktmax) load_kv(kt + 2);
        asm volatile("cp.async.commit_group;");
    }

    float inv0 = 1.f / lrow[0];
    float inv1 = 1.f / lrow[1];
    long row0 = (long)(b * S_ + qt * 128 + w * 16 + (lane >> 2));
    long cbase = (long)h * 128 + (lane & 3) * 2;
#pragma unroll
    for (int t = 0; t < 16; t++) {
        long off0 = row0 * (NH_ * HD_) + cbase + t * 8;
        long off1 = off0 + 8L * (NH_ * HD_);
        float v0 = oacc[t][0] * inv0, v1 = oacc[t][1] * inv0;
        float v2 = oacc[t][2] * inv1, v3 = oacc[t][3] * inv1;
        __half2 h0 = __floats2half2_rn(v0, v1);
        __half2 h1 = __floats2half2_rn(v2, v3);
        float2 f0 = __half22float2(h0);
        float2 f1 = __half22float2(h1);
        __half2 l0 = __floats2half2_rn(v0 - f0.x, v1 - f0.y);
        __half2 l1 = __floats2half2_rn(v2 - f1.x, v3 - f1.y);
        *(uint32_t*)(g_Ohi + off0) = *(uint32_t*)&h0;
        *(uint32_t*)(g_Ohi + off1) = *(uint32_t*)&h1;
        *(uint32_t*)(g_Olo + off0) = *(uint32_t*)&l0;
        *(uint32_t*)(g_Olo + off1) = *(uint32_t*)&l1;
    }
}

// ---------------------------------------------------------------------------
extern "C" void kernel_launch(void* const* d_in, const int* in_sizes, int n_in,
                              void* d_out, int out_size)
{
    const float* hidden = (const float*)d_in[0];
    const float* cosb   = (const float*)d_in[1];
    const float* sinb   = (const float*)d_in[2];
    const float* Wq = (const float*)d_in[4];
    const float* Wk = (const float*)d_in[5];
    const float* Wv = (const float*)d_in[6];
    const float* Wo = (const float*)d_in[7];
    float* out = (float*)d_out;

    __half *pAhi, *pAlo, *pWhi, *pWlo, *pWOhi, *pWOlo, *pOhi, *pOlo;
    cudaGetSymbolAddress((void**)&pAhi, g_Ahi);
    cudaGetSymbolAddress((void**)&pAlo, g_Alo);
    cudaGetSymbolAddress((void**)&pWhi, g_Whi);
    cudaGetSymbolAddress((void**)&pWlo, g_Wlo);
    cudaGetSymbolAddress((void**)&pWOhi, g_WOhi);
    cudaGetSymbolAddress((void**)&pWOlo, g_WOlo);
    cudaGetSymbolAddress((void**)&pOhi, g_Ohi);
    cudaGetSymbolAddress((void**)&pOlo, g_Olo);

    cudaFuncSetAttribute(hgemm<0>, cudaFuncAttributeMaxDynamicSharedMemorySize, HGEMM_SMEM);
    cudaFuncSetAttribute(hgemm<1>, cudaFuncAttributeMaxDynamicSharedMemorySize, HGEMM_SMEM);
    cudaFuncSetAttribute(attn_mma_kernel, cudaFuncAttributeMaxDynamicSharedMemorySize, ATT_SMEM);

    // 1) fp16 splits of activations and weights
    int n4;
    n4 = MTOK * HID_ / 4;
    split_kernel<<<(n4 + 255) / 256, 256>>>(hidden, pAhi, pAlo, n4);
    n4 = NH_ * HD_ * HID_ / 4;
    split_kernel<<<(n4 + 255) / 256, 256>>>(Wq, pWhi, pWlo, n4);
    n4 = NKV_ * HD_ * HID_ / 4;
    split_kernel<<<(n4 + 255) / 256, 256>>>(Wk, pWhi + (long)NH_ * HD_ * HID_,
                                            pWlo + (long)NH_ * HD_ * HID_, n4);
    split_kernel<<<(n4 + 255) / 256, 256>>>(Wv, pWhi + (long)(NH_ + NKV_) * HD_ * HID_,
                                            pWlo + (long)(NH_ + NKV_) * HD_ * HID_, n4);
    n4 = HID_ * HID_ / 4;
    split_kernel<<<(n4 + 255) / 256, 256>>>(Wo, pWOhi, pWOlo, n4);

    // 2) QKV projection (tensor cores) + scatter
    hgemm<1><<<dim3(NQKV / BN2, MTOK / BM2), 256, HGEMM_SMEM>>>(
        pAhi, pAlo, pWhi, pWlo, nullptr, MTOK, NQKV, HID_);

    // 3) RoPE + split-fp16 conversion of Q, K, V
    int total = QPAIRS + 2 * KPAIRS;
    rope_conv_kernel<<<(total + 255) / 256, 256>>>(cosb, sinb);

    // 4) Tensor-core causal flash attention
    attn_mma_kernel<<<dim3(S_ / 128, B_ * NH_), 256, ATT_SMEM>>>();

    // 5) Output projection (tensor cores)
    hgemm<0><<<dim3(HID_ / BN2, MTOK / BM2), 256, HGEMM_SMEM>>>(
        pOhi, pOlo, pWOhi, pWOlo, out, MTOK, HID_, HID_);
}

// round 10
// speedup vs baseline: 1.3052x; 1.3052x over previous
#include <cuda_runtime.h>
#include <cuda_fp16.h>
#include <cstdint>
#include <math.h>

// Problem constants
#define B_    2
#define S_    2048
#define HID_  4096
#define NH_   32
#define NKV_  8
#define HD_   128
#define MTOK  (B_ * S_)                    // 4096
#define NQKV  (NH_ * HD_ + 2 * NKV_ * HD_) // 6144
#define SCALING 0.08838834764831845f
#define LOG2E  1.4426950408889634f

// fp32 scratch (QKV projection output, pre-rope)
__device__ float g_Q[B_ * NH_ * S_ * HD_];
__device__ float g_K[B_ * NKV_ * S_ * HD_];
__device__ float g_V[B_ * NKV_ * S_ * HD_];

// split-fp16 post-rope QKV for attention
__device__ __half g_Qh[B_ * NH_ * S_ * HD_];
__device__ __half g_Ql[B_ * NH_ * S_ * HD_];
__device__ __half g_Kh[B_ * NKV_ * S_ * HD_];
__device__ __half g_Kl[B_ * NKV_ * S_ * HD_];
__device__ __half g_Vh[B_ * NKV_ * S_ * HD_];
__device__ __half g_Vl[B_ * NKV_ * S_ * HD_];

// fp16 split scratch for projections
__device__ __half g_Ahi[MTOK * HID_];
__device__ __half g_Alo[MTOK * HID_];
__device__ __half g_Whi[NQKV * HID_];
__device__ __half g_Wlo[NQKV * HID_];
__device__ __half g_WOhi[HID_ * HID_];
__device__ __half g_WOlo[HID_ * HID_];
__device__ __half g_Ohi[MTOK * HID_];   // attention out, hi (PASSES=2: no lo needed)
__device__ __half g_Olo[MTOK * HID_];   // unused by out-proj now (kept for layout)

// ---------------------------------------------------------------------------
__global__ __launch_bounds__(256) void split_kernel(
    const float* __restrict__ src, __half* __restrict__ hi,
    __half* __restrict__ lo, int n4)
{
    int i = blockIdx.x * 256 + threadIdx.x;
    if (i >= n4) return;
    float4 v = ((const float4*)src)[i];
    __half h0 = __float2half_rn(v.x);
    __half h1 = __float2half_rn(v.y);
    __half h2 = __float2half_rn(v.z);
    __half h3 = __float2half_rn(v.w);
    __half l0 = __float2half_rn(v.x - __half2float(h0));
    __half l1 = __float2half_rn(v.y - __half2float(h1));
    __half l2 = __float2half_rn(v.z - __half2float(h2));
    __half l3 = __float2half_rn(v.w - __half2float(h3));
    ((__half2*)hi)[2 * i + 0] = __halves2half2(h0, h1);
    ((__half2*)hi)[2 * i + 1] = __halves2half2(h2, h3);
    ((__half2*)lo)[2 * i + 0] = __halves2half2(l0, l1);
    ((__half2*)lo)[2 * i + 1] = __halves2half2(l2, l3);
}

// ---------------------------------------------------------------------------
// Split-fp16 tensor-core GEMM: C[M,N] = A[M,K] @ B[N,K]^T  (fp32 result)
// 128x128x32 block tile, 256 threads (8 warps, 2x4), warp tile 64x32,
// mma.sync.m16n8k16, cp.async double buffering.
// PASSES=3: AhBh + AhBl + AlBh.  PASSES=2: AhBh + AhBl (Al unused entirely).
// MODE 0: plain store; MODE 1: QKV scatter into g_Q/g_K/g_V.
// ---------------------------------------------------------------------------
#define BM 128
#define BN 128
#define BKc 32
#define SSTRIDE 40                     // fp16 elems per smem row (conflict-free)
#define TILEB (128 * SSTRIDE * 2)      // bytes per (array, stage) tile = 10240
#define HGEMM_SMEM (2 * 4 * TILEB)     // 81920 bytes

#define LDMX4(R0, R1, R2, R3, ADDR)                                          \
    asm volatile("ldmatrix.sync.aligned.m8n8.x4.shared.b16 {%0,%1,%2,%3}, [%4];" \
                 : "=r"(R0), "=r"(R1), "=r"(R2), "=r"(R3) : "r"(ADDR))

#define LDMX4T(R0, R1, R2, R3, ADDR)                                         \
    asm volatile("ldmatrix.sync.aligned.m8n8.x4.trans.shared.b16 {%0,%1,%2,%3}, [%4];" \
                 : "=r"(R0), "=r"(R1), "=r"(R2), "=r"(R3) : "r"(ADDR))

#define MMA16816(C, A, B0, B1)                                               \
    asm volatile("mma.sync.aligned.m16n8k16.row.col.f32.f16.f16.f32 "        \
                 "{%0,%1,%2,%3}, {%4,%5,%6,%7}, {%8,%9}, {%0,%1,%2,%3};"     \
                 : "+f"(C[0]), "+f"(C[1]), "+f"(C[2]), "+f"(C[3])            \
                 : "r"(A[0]), "r"(A[1]), "r"(A[2]), "r"(A[3]), "r"(B0), "r"(B1))

template <int MODE, int PASSES>
__global__ __launch_bounds__(256) void hgemm(
    const __half* __restrict__ Ah, const __half* __restrict__ Al,
    const __half* __restrict__ Bh, const __half* __restrict__ Bl,
    float* __restrict__ C, int M, int N, int K)
{
    extern __shared__ __half smh[];
    const unsigned smem_base = (unsigned)__cvta_generic_to_shared(smh);

    const int tid = threadIdx.x;
    const int lane = tid & 31;
    const int wid = tid >> 5;
    const int wm = wid >> 2;    // 0..1
    const int wn = wid & 3;     // 0..3
    const int m0 = blockIdx.y * BM;
    const int n0 = blockIdx.x * BN;

    const __half* gsrc[4];
    gsrc[0] = Ah + (long)m0 * K;
    gsrc[1] = Al + (long)m0 * K;
    gsrc[2] = Bh + (long)n0 * K;
    gsrc[3] = Bl + (long)n0 * K;

    const int r0 = tid >> 2;        // 0..63
    const int c0 = tid & 3;         // 16B chunk index within 64B row

    auto load_stage = [&](int stage, int k0) {
        unsigned sbase = smem_base + stage * 4 * TILEB;
#pragma unroll
        for (int a = 0; a < 4; a++) {
            if (PASSES == 2 && a == 1) continue;   // Al never used
#pragma unroll
            for (int t = 0; t < 2; t++) {
                int row = r0 + t * 64;
                const __half* g = gsrc[a] + (long)row * K + k0 + c0 * 8;
                unsigned s = sbase + a * TILEB + (row * SSTRIDE + c0 * 8) * 2;
                asm volatile("cp.async.ca.shared.global [%0], [%1], 16;"
                             :: "r"(s), "l"(g));
            }
        }
    };

    float acc[4][4][4];
#pragma unroll
    for (int i = 0; i < 4; i++)
#pragma unroll
        for (int j = 0; j < 4; j++)
#pragma unroll
            for (int r = 0; r < 4; r++) acc[i][j][r] = 0.f;

    const int nk = K / BKc;
    load_stage(0, 0);
    asm volatile("cp.async.commit_group;");
    load_stage(1, BKc);
    asm volatile("cp.async.commit_group;");

    for (int kc = 0; kc < nk; kc++) {
        int stage = kc & 1;
        asm volatile("cp.async.wait_group 1;");
        __syncthreads();

        unsigned sbase = smem_base + stage * 4 * TILEB;
        unsigned uAh = sbase;
        unsigned uAl = sbase + TILEB;
        unsigned uBh = sbase + 2 * TILEB;
        unsigned uBl = sbase + 3 * TILEB;

#pragma unroll
        for (int ks = 0; ks < 2; ks++) {
            const int kcol = ks * 16 + (lane >> 4) * 8;
            uint32_t afh[4][4], afl[4][4];
#pragma unroll
            for (int mi = 0; mi < 4; mi++) {
                int arow = wm * 64 + mi * 16 + (lane & 15);
                unsigned off = (arow * SSTRIDE + kcol) * 2;
                LDMX4(afh[mi][0], afh[mi][1], afh[mi][2], afh[mi][3], uAh + off);
                if (PASSES == 3) {
                    LDMX4(afl[mi][0], afl[mi][1], afl[mi][2], afl[mi][3], uAl + off);
                }
            }
            uint32_t bfh[4][2], bfl[4][2];
#pragma unroll
            for (int p = 0; p < 2; p++) {
                int brow = wn * 32 + p * 16 + (lane & 15);
                unsigned off = (brow * SSTRIDE + kcol) * 2;
                uint32_t t0, t1, t2, t3;
                LDMX4(t0, t1, t2, t3, uBh + off);
                bfh[p * 2][0] = t0; bfh[p * 2][1] = t2;
                bfh[p * 2 + 1][0] = t1; bfh[p * 2 + 1][1] = t3;
                LDMX4(t0, t1, t2, t3, uBl + off);
                bfl[p * 2][0] = t0; bfl[p * 2][1] = t2;
                bfl[p * 2 + 1][0] = t1; bfl[p * 2 + 1][1] = t3;
            }
#pragma unroll
            for (int mi = 0; mi < 4; mi++)
#pragma unroll
                for (int nj = 0; nj < 4; nj++) {
                    MMA16816(acc[mi][nj], afh[mi], bfh[nj][0], bfh[nj][1]);
                    MMA16816(acc[mi][nj], afh[mi], bfl[nj][0], bfl[nj][1]);
                    if (PASSES == 3) {
                        MMA16816(acc[mi][nj], afl[mi], bfh[nj][0], bfh[nj][1]);
                    }
                }
        }
        __syncthreads();
        int knext = (kc + 2) * BKc;
        if (knext < K) load_stage(stage, knext);
        asm volatile("cp.async.commit_group;");
    }

    // Epilogue
    const int lr = lane >> 2;
    const int lc = (lane & 3) * 2;
#pragma unroll
    for (int mi = 0; mi < 4; mi++) {
        int rbase = m0 + wm * 64 + mi * 16;
#pragma unroll
        for (int hf = 0; hf < 2; hf++) {
            int row = rbase + lr + hf * 8;
            float* dst;
            if (MODE == 0) {
                dst = C + (long)row * N + n0;
            } else {
                int b = row >> 11;
                int s = row & 2047;
                if (n0 < NH_ * HD_) {
                    int h = n0 >> 7;
                    dst = g_Q + (((long)(b * NH_ + h) * S_ + s) << 7);
                } else if (n0 < NH_ * HD_ + NKV_ * HD_) {
                    int h = (n0 - NH_ * HD_) >> 7;
                    dst = g_K + (((long)(b * NKV_ + h) * S_ + s) << 7);
                } else {
                    int h = (n0 - NH_ * HD_ - NKV_ * HD_) >> 7;
                    dst = g_V + (((long)(b * NKV_ + h) * S_ + s) << 7);
                }
            }
#pragma unroll
            for (int nj = 0; nj < 4; nj++) {
                int col = wn * 32 + nj * 8 + lc;
                float2 v = make_float2(acc[mi][nj][hf * 2 + 0],
                                       acc[mi][nj][hf * 2 + 1]);
                *(float2*)(dst + col) = v;
            }
        }
    }
}

// ---------------------------------------------------------------------------
// RoPE + split-fp16 convert
// ---------------------------------------------------------------------------
#define QPAIRS (B_ * NH_ * S_ * 64)
#define KPAIRS (B_ * NKV_ * S_ * 64)

__device__ __forceinline__ void split2w(float v, __half* ph, __half* pl, long off)
{
    __half h = __float2half_rn(v);
    ph[off] = h;
    pl[off] = __float2half_rn(v - __half2float(h));
}

__global__ __launch_bounds__(256) void rope_conv_kernel(
    const float* __restrict__ cosb, const float* __restrict__ sinb)
{
    int idx = blockIdx.x * 256 + threadIdx.x;
    if (idx < QPAIRS) {
        int d = idx & 63;
        int s = (idx >> 6) & 2047;
        int h = (idx >> 17) & 31;
        int b = idx >> 22;
        long base = ((long)(b * NH_ + h) * S_ + s) << 7;
        float c  = cosb[((long)(b * S_ + s) << 7) + d];
        float sn = sinb[((long)(b * S_ + s) << 7) + d];
        float x1 = g_Q[base + d];
        float x2 = g_Q[base + d + 64];
        split2w(x1 * c - x2 * sn, g_Qh, g_Ql, base + d);
        split2w(x2 * c + x1 * sn, g_Qh, g_Ql, base + d + 64);
    } else if (idx < QPAIRS + KPAIRS) {
        int i2 = idx - QPAIRS;
        int d = i2 & 63;
        int s = (i2 >> 6) & 2047;
        int h = (i2 >> 17) & 7;
        int b = i2 >> 20;
        long base = ((long)(b * NKV_ + h) * S_ + s) << 7;
        float c  = cosb[((long)(b * S_ + s) << 7) + d];
        float sn = sinb[((long)(b * S_ + s) << 7) + d];
        float x1 = g_K[base + d];
        float x2 = g_K[base + d + 64];
        split2w(x1 * c - x2 * sn, g_Kh, g_Kl, base + d);
        split2w(x2 * c + x1 * sn, g_Kh, g_Kl, base + d + 64);
    } else if (idx < QPAIRS + 2 * KPAIRS) {
        int i3 = idx - QPAIRS - KPAIRS;
        int d = i3 & 63;
        int s = (i3 >> 6) & 2047;
        int h = (i3 >> 17) & 7;
        int b = i3 >> 20;
        long base = ((long)(b * NKV_ + h) * S_ + s) << 7;
        split2w(g_V[base + d],      g_Vh, g_Vl, base + d);
        split2w(g_V[base + d + 64], g_Vh, g_Vl, base + d + 64);
    }
}

// ---------------------------------------------------------------------------
// FFMA-only exp2 (no MUFU). x <= 0 expected; rel err ~2e-5.
// ---------------------------------------------------------------------------
__device__ __forceinline__ float exp2p(float x)
{
    x = fmaxf(x, -120.f);
    float fl = floorf(x);
    float f = x - fl;
    float p = 1.5403530393381606e-4f;
    p = fmaf(p, f, 1.3333558146428443e-3f);
    p = fmaf(p, f, 9.6181291076284770e-3f);
    p = fmaf(p, f, 5.5504108664821580e-2f);
    p = fmaf(p, f, 2.4022650695910070e-1f);
    p = fmaf(p, f, 6.9314718055994531e-1f);
    p = fmaf(p, f, 1.0f);
    return __int_as_float(__float_as_int(p) + (((int)fl) << 23));
}

// ---------------------------------------------------------------------------
// Tensor-core causal flash attention (R4-proven), epilogue writes hi only.
// ---------------------------------------------------------------------------
#define ASTR 136
#define QH_B  0
#define QL_B  (128 * ASTR * 2)
#define STG_B (2 * 128 * ASTR * 2)
#define AKH_B 0
#define AKL_B (64 * ASTR * 2)
#define AVH_B (2 * 64 * ASTR * 2)
#define AVL_B (3 * 64 * ASTR * 2)
#define STG_SZB (4 * 64 * ASTR * 2)
#define ATT_SMEM (STG_B + 2 * STG_SZB)

__global__ __launch_bounds__(256, 1) void attn_mma_kernel()
{
    extern __shared__ __half sm[];
    const unsigned sbase = (unsigned)__cvta_generic_to_shared(sm);
    const int tid = threadIdx.x;
    const int lane = tid & 31;
    const int w = tid >> 5;
    const int qt = gridDim.x - 1 - blockIdx.x;
    const int bh = blockIdx.y;
    const int b = bh >> 5;
    const int h = bh & 31;
    const int hk = h >> 2;

    const __half* Qhp = g_Qh + ((long)(b * NH_ + h) * S_ << 7);
    const __half* Qlp = g_Ql + ((long)(b * NH_ + h) * S_ << 7);
    const __half* Khp = g_Kh + ((long)(b * NKV_ + hk) * S_ << 7);
    const __half* Klp = g_Kl + ((long)(b * NKV_ + hk) * S_ << 7);
    const __half* Vhp = g_Vh + ((long)(b * NKV_ + hk) * S_ << 7);
    const __half* Vlp = g_Vl + ((long)(b * NKV_ + hk) * S_ << 7);

    const int ktmax = 2 * qt + 1;
    const int rr = tid >> 4;
    const int cc = (tid & 15) * 8;

    auto cpa = [&](unsigned sboff, const __half* g) {
        asm volatile("cp.async.ca.shared.global [%0], [%1], 16;"
                     :: "r"(sbase + sboff), "l"(g));
    };
    auto load_kv = [&](int kt) {
        unsigned st = STG_B + (kt & 1) * STG_SZB;
        const __half* kb = Khp + (long)kt * 64 * 128;
        const __half* lb = Klp + (long)kt * 64 * 128;
        const __half* vb = Vhp + (long)kt * 64 * 128;
        const __half* wb = Vlp + (long)kt * 64 * 128;
#pragma unroll
        for (int it = 0; it < 4; it++) {
            int row = rr + it * 16;
            unsigned ro = (row * ASTR) * 2 + cc * 2;
            cpa(st + AKH_B + ro, kb + row * 128 + cc);
            cpa(st + AKL_B + ro, lb + row * 128 + cc);
            cpa(st + AVH_B + ro, vb + row * 128 + cc);
            cpa(st + AVL_B + ro, wb + row * 128 + cc);
        }
    };

    {
#pragma unroll
        for (int it = 0; it < 8; it++) {
            int row = rr + it * 16;
            unsigned ro = (row * ASTR) * 2 + cc * 2;
            cpa(QH_B + ro, Qhp + (long)(qt * 128 + row) * 128 + cc);
            cpa(QL_B + ro, Qlp + (long)(qt * 128 + row) * 128 + cc);
        }
        load_kv(0);
    }
    asm volatile("cp.async.commit_group;");
    load_kv(1);
    asm volatile("cp.async.commit_group;");

    float oacc[16][4];
#pragma unroll
    for (int t = 0; t < 16; t++)
#pragma unroll
        for (int e = 0; e < 4; e++) oacc[t][e] = 0.f;
    float mrow[2] = {-1e30f, -1e30f};
    float lrow[2] = {0.f, 0.f};

    const int qrow0 = qt * 128 + w * 16 + (lane >> 2);
    const float SL = SCALING * LOG2E;

    for (int kt = 0; kt <= ktmax; kt++) {
        asm volatile("cp.async.wait_group 1;");
        __syncthreads();

        unsigned st = sbase + STG_B + (kt & 1) * STG_SZB;

        float sacc[8][4];
#pragma unroll
        for (int j = 0; j < 8; j++)
#pragma unroll
            for (int e = 0; e < 4; e++) sacc[j][e] = 0.f;

#pragma unroll
        for (int ks = 0; ks < 8; ks++) {
            const int kcol = ks * 16 + (lane >> 4) * 8;
            unsigned aoff = ((w * 16 + (lane & 15)) * ASTR + kcol) * 2;
            uint32_t ah[4], al[4];
            LDMX4(ah[0], ah[1], ah[2], ah[3], sbase + QH_B + aoff);
            LDMX4(al[0], al[1], al[2], al[3], sbase + QL_B + aoff);
#pragma unroll
            for (int p = 0; p < 4; p++) {
                unsigned boff = ((p * 16 + (lane & 15)) * ASTR + kcol) * 2;
                uint32_t t0, t1, t2, t3, u0, u1, u2, u3;
                LDMX4(t0, t1, t2, t3, st + AKH_B + boff);
                LDMX4(u0, u1, u2, u3, st + AKL_B + boff);
                MMA16816(sacc[2 * p],     ah, t0, t2);
                MMA16816(sacc[2 * p],     al, t0, t2);
                MMA16816(sacc[2 * p],     ah, u0, u2);
                MMA16816(sacc[2 * p + 1], ah, t1, t3);
                MMA16816(sacc[2 * p + 1], al, t1, t3);
                MMA16816(sacc[2 * p + 1], ah, u1, u3);
            }
        }

        const bool diag = (kt >= 2 * qt);
        float rmax[2] = {-1e30f, -1e30f};
#pragma unroll
        for (int j = 0; j < 8; j++)
#pragma unroll
            for (int e = 0; e < 4; e++) {
                float v = sacc[j][e] * SL;
                if (diag) {
                    int col = kt * 64 + j * 8 + (lane & 3) * 2 + (e & 1);
                    int row = qrow0 + (e >> 1) * 8;
                    if (col > row) v = -1e30f;
                }
                sacc[j][e] = v;
                rmax[e >> 1] = fmaxf(rmax[e >> 1], v);
            }
#pragma unroll
        for (int r = 0; r < 2; r++) {
            rmax[r] = fmaxf(rmax[r], __shfl_xor_sync(0xffffffffu, rmax[r], 1));
            rmax[r] = fmaxf(rmax[r], __shfl_xor_sync(0xffffffffu, rmax[r], 2));
        }
        float mn0 = fmaxf(mrow[0], rmax[0]);
        float mn1 = fmaxf(mrow[1], rmax[1]);
        float al0 = exp2p(mrow[0] - mn0);
        float al1 = exp2p(mrow[1] - mn1);
        mrow[0] = mn0; mrow[1] = mn1;

        uint32_t ph[8][2], pl[8][2];
        float ls0 = 0.f, ls1 = 0.f;
#pragma unroll
        for (int j = 0; j < 8; j++) {
            float p0 = exp2p(sacc[j][0] - mn0);
            float p1 = exp2p(sacc[j][1] - mn0);
            float p2 = exp2p(sacc[j][2] - mn1);
            float p3 = exp2p(sacc[j][3] - mn1);
            ls0 += p0 + p1;
            ls1 += p2 + p3;
            __half2 h01 = __floats2half2_rn(p0, p1);
            __half2 h23 = __floats2half2_rn(p2, p3);
            ph[j][0] = *(uint32_t*)&h01;
            ph[j][1] = *(uint32_t*)&h23;
            float2 f01 = __half22float2(h01);
            float2 f23 = __half22float2(h23);
            __half2 l01 = __floats2half2_rn(p0 - f01.x, p1 - f01.y);
            __half2 l23 = __floats2half2_rn(p2 - f23.x, p3 - f23.y);
            pl[j][0] = *(uint32_t*)&l01;
            pl[j][1] = *(uint32_t*)&l23;
        }
        ls0 += __shfl_xor_sync(0xffffffffu, ls0, 1);
        ls0 += __shfl_xor_sync(0xffffffffu, ls0, 2);
        ls1 += __shfl_xor_sync(0xffffffffu, ls1, 1);
        ls1 += __shfl_xor_sync(0xffffffffu, ls1, 2);
        lrow[0] = lrow[0] * al0 + ls0;
        lrow[1] = lrow[1] * al1 + ls1;
#pragma unroll
        for (int t = 0; t < 16; t++) {
            oacc[t][0] *= al0; oacc[t][1] *= al0;
            oacc[t][2] *= al1; oacc[t][3] *= al1;
        }

#pragma unroll
        for (int dk = 0; dk < 4; dk++) {
            uint32_t aPh[4] = {ph[2 * dk][0], ph[2 * dk][1],
                               ph[2 * dk + 1][0], ph[2 * dk + 1][1]};
            uint32_t aPl[4] = {pl[2 * dk][0], pl[2 * dk][1],
                               pl[2 * dk + 1][0], pl[2 * dk + 1][1]};
#pragma unroll
            for (int np = 0; np < 8; np++) {
                unsigned vo = ((dk * 16 + (lane & 15)) * ASTR +
                               np * 16 + (lane >> 4) * 8) * 2;
                uint32_t t0, t1, t2, t3, u0, u1, u2, u3;
                LDMX4T(t0, t1, t2, t3, st + AVH_B + vo);
                LDMX4T(u0, u1, u2, u3, st + AVL_B + vo);
                MMA16816(oacc[2 * np],     aPh, t0, t1);
                MMA16816(oacc[2 * np],     aPh, u0, u1);
                MMA16816(oacc[2 * np],     aPl, t0, t1);
                MMA16816(oacc[2 * np + 1], aPh, t2, t3);
                MMA16816(oacc[2 * np + 1], aPh, u2, u3);
                MMA16816(oacc[2 * np + 1], aPl, t2, t3);
            }
        }

        __syncthreads();
        if (kt + 2 <= ktmax) load_kv(kt + 2);
        asm volatile("cp.async.commit_group;");
    }

    // finalize: write hi-only split O in [b*s][h*d] layout
    float inv0 = 1.f / lrow[0];
    float inv1 = 1.f / lrow[1];
    long row0 = (long)(b * S_ + qt * 128 + w * 16 + (lane >> 2));
    long cbase = (long)h * 128 + (lane & 3) * 2;
#pragma unroll
    for (int t = 0; t < 16; t++) {
        long off0 = row0 * (NH_ * HD_) + cbase + t * 8;
        long off1 = off0 + 8L * (NH_ * HD_);
        float v0 = oacc[t][0] * inv0, v1 = oacc[t][1] * inv0;
        float v2 = oacc[t][2] * inv1, v3 = oacc[t][3] * inv1;
        __half2 h0 = __floats2half2_rn(v0, v1);
        __half2 h1 = __floats2half2_rn(v2, v3);
        *(uint32_t*)(g_Ohi + off0) = *(uint32_t*)&h0;
        *(uint32_t*)(g_Ohi + off1) = *(uint32_t*)&h1;
    }
}

// ---------------------------------------------------------------------------
extern "C" void kernel_launch(void* const* d_in, const int* in_sizes, int n_in,
                              void* d_out, int out_size)
{
    const float* hidden = (const float*)d_in[0];
    const float* cosb   = (const float*)d_in[1];
    const float* sinb   = (const float*)d_in[2];
    const float* Wq = (const float*)d_in[4];
    const float* Wk = (const float*)d_in[5];
    const float* Wv = (const float*)d_in[6];
    const float* Wo = (const float*)d_in[7];
    float* out = (float*)d_out;

    __half *pAhi, *pAlo, *pWhi, *pWlo, *pWOhi, *pWOlo, *pOhi, *pOlo;
    cudaGetSymbolAddress((void**)&pAhi, g_Ahi);
    cudaGetSymbolAddress((void**)&pAlo, g_Alo);
    cudaGetSymbolAddress((void**)&pWhi, g_Whi);
    cudaGetSymbolAddress((void**)&pWlo, g_Wlo);
    cudaGetSymbolAddress((void**)&pWOhi, g_WOhi);
    cudaGetSymbolAddress((void**)&pWOlo, g_WOlo);
    cudaGetSymbolAddress((void**)&pOhi, g_Ohi);
    cudaGetSymbolAddress((void**)&pOlo, g_Olo);

    cudaFuncSetAttribute((const void*)hgemm<0, 2>, cudaFuncAttributeMaxDynamicSharedMemorySize, HGEMM_SMEM);
    cudaFuncSetAttribute((const void*)hgemm<1, 3>, cudaFuncAttributeMaxDynamicSharedMemorySize, HGEMM_SMEM);
    cudaFuncSetAttribute(attn_mma_kernel, cudaFuncAttributeMaxDynamicSharedMemorySize, ATT_SMEM);

    // 1) fp16 splits of activations and weights
    int n4;
    n4 = MTOK * HID_ / 4;
    split_kernel<<<(n4 + 255) / 256, 256>>>(hidden, pAhi, pAlo, n4);
    n4 = NH_ * HD_ * HID_ / 4;
    split_kernel<<<(n4 + 255) / 256, 256>>>(Wq, pWhi, pWlo, n4);
    n4 = NKV_ * HD_ * HID_ / 4;
    split_kernel<<<(n4 + 255) / 256, 256>>>(Wk, pWhi + (long)NH_ * HD_ * HID_,
                                            pWlo + (long)NH_ * HD_ * HID_, n4);
    split_kernel<<<(n4 + 255) / 256, 256>>>(Wv, pWhi + (long)(NH_ + NKV_) * HD_ * HID_,
                                            pWlo + (long)(NH_ + NKV_) * HD_ * HID_, n4);
    n4 = HID_ * HID_ / 4;
    split_kernel<<<(n4 + 255) / 256, 256>>>(Wo, pWOhi, pWOlo, n4);

    // 2) QKV projection (tensor cores, 3-pass) + scatter
    hgemm<1, 3><<<dim3(NQKV / BN, MTOK / BM), 256, HGEMM_SMEM>>>(
        pAhi, pAlo, pWhi, pWlo, nullptr, MTOK, NQKV, HID_);

    // 3) RoPE + split-fp16 conversion of Q, K, V
    int total = QPAIRS + 2 * KPAIRS;
    rope_conv_kernel<<<(total + 255) / 256, 256>>>(cosb, sinb);

    // 4) Tensor-core causal flash attention
    attn_mma_kernel<<<dim3(S_ / 128, B_ * NH_), 256, ATT_SMEM>>>();

    // 5) Output projection (tensor cores, 2-pass: Ohi*(WOhi+WOlo))
    hgemm<0, 2><<<dim3(HID_ / BN, MTOK / BM), 256, HGEMM_SMEM>>>(
        pOhi, pOlo, pWOhi, pWOlo, out, MTOK, HID_, HID_);
}

// round 12
// speedup vs baseline: 1.5702x; 1.2030x over previous
#include <cuda_runtime.h>
#include <cuda_fp16.h>
#include <cstdint>
#include <math.h>

// Problem constants
#define B_    2
#define S_    2048
#define HID_  4096
#define NH_   32
#define NKV_  8
#define HD_   128
#define MTOK  (B_ * S_)                    // 4096
#define NQKV  (NH_ * HD_ + 2 * NKV_ * HD_) // 6144
#define SCALING 0.08838834764831845f
#define LOG2E  1.4426950408889634f

// fp32 scratch (QKV projection output, pre-rope)
__device__ float g_Q[B_ * NH_ * S_ * HD_];
__device__ float g_K[B_ * NKV_ * S_ * HD_];
__device__ float g_V[B_ * NKV_ * S_ * HD_];

// split-fp16 post-rope QKV for attention
__device__ __half g_Qh[B_ * NH_ * S_ * HD_];
__device__ __half g_Ql[B_ * NH_ * S_ * HD_];
__device__ __half g_Kh[B_ * NKV_ * S_ * HD_];
__device__ __half g_Kl[B_ * NKV_ * S_ * HD_];
__device__ __half g_Vh[B_ * NKV_ * S_ * HD_];
__device__ __half g_Vl[B_ * NKV_ * S_ * HD_];

// fp16 split scratch for projections
__device__ __half g_Ahi[MTOK * HID_];
__device__ __half g_Alo[MTOK * HID_];
__device__ __half g_Whi[NQKV * HID_];
__device__ __half g_Wlo[NQKV * HID_];
__device__ __half g_WOhi[HID_ * HID_];
__device__ __half g_WOlo[HID_ * HID_];
__device__ __half g_Ohi[MTOK * HID_];   // attention out, hi
__device__ __half g_Olo[MTOK * HID_];   // unused (kept for layout)

// ---------------------------------------------------------------------------
__global__ __launch_bounds__(256) void split_kernel(
    const float* __restrict__ src, __half* __restrict__ hi,
    __half* __restrict__ lo, int n4)
{
    int i = blockIdx.x * 256 + threadIdx.x;
    if (i >= n4) return;
    float4 v = ((const float4*)src)[i];
    __half h0 = __float2half_rn(v.x);
    __half h1 = __float2half_rn(v.y);
    __half h2 = __float2half_rn(v.z);
    __half h3 = __float2half_rn(v.w);
    __half l0 = __float2half_rn(v.x - __half2float(h0));
    __half l1 = __float2half_rn(v.y - __half2float(h1));
    __half l2 = __float2half_rn(v.z - __half2float(h2));
    __half l3 = __float2half_rn(v.w - __half2float(h3));
    ((__half2*)hi)[2 * i + 0] = __halves2half2(h0, h1);
    ((__half2*)hi)[2 * i + 1] = __halves2half2(h2, h3);
    ((__half2*)lo)[2 * i + 0] = __halves2half2(l0, l1);
    ((__half2*)lo)[2 * i + 1] = __halves2half2(l2, l3);
}

// ---------------------------------------------------------------------------
// Split-fp16 tensor-core GEMM: C[M,N] = A[M,K] @ B[N,K]^T  (fp32 result)
// 128x128x32 block tile, 256 threads (8 warps, 2x4), warp tile 64x32,
// mma.sync.m16n8k16, cp.async double buffering.
// PASSES=3: AhBh + AhBl + AlBh.  PASSES=2: AhBh + AhBl (Al unused entirely).
// MODE 0: plain store; MODE 1: QKV scatter into g_Q/g_K/g_V.
// ---------------------------------------------------------------------------
#define BM 128
#define BN 128
#define BKc 32
#define SSTRIDE 40                     // fp16 elems per smem row (conflict-free)
#define TILEB (128 * SSTRIDE * 2)      // bytes per (array, stage) tile = 10240
#define HGEMM_SMEM (2 * 4 * TILEB)     // 81920 bytes

#define LDMX4(R0, R1, R2, R3, ADDR)                                          \
    asm volatile("ldmatrix.sync.aligned.m8n8.x4.shared.b16 {%0,%1,%2,%3}, [%4];" \
                 : "=r"(R0), "=r"(R1), "=r"(R2), "=r"(R3) : "r"(ADDR))

#define LDMX4T(R0, R1, R2, R3, ADDR)                                         \
    asm volatile("ldmatrix.sync.aligned.m8n8.x4.trans.shared.b16 {%0,%1,%2,%3}, [%4];" \
                 : "=r"(R0), "=r"(R1), "=r"(R2), "=r"(R3) : "r"(ADDR))

#define MMA16816(C, A, B0, B1)                                               \
    asm volatile("mma.sync.aligned.m16n8k16.row.col.f32.f16.f16.f32 "        \
                 "{%0,%1,%2,%3}, {%4,%5,%6,%7}, {%8,%9}, {%0,%1,%2,%3};"     \
                 : "+f"(C[0]), "+f"(C[1]), "+f"(C[2]), "+f"(C[3])            \
                 : "r"(A[0]), "r"(A[1]), "r"(A[2]), "r"(A[3]), "r"(B0), "r"(B1))

template <int MODE, int PASSES>
__global__ __launch_bounds__(256) void hgemm(
    const __half* __restrict__ Ah, const __half* __restrict__ Al,
    const __half* __restrict__ Bh, const __half* __restrict__ Bl,
    float* __restrict__ C, int M, int N, int K)
{
    extern __shared__ __half smh[];
    const unsigned smem_base = (unsigned)__cvta_generic_to_shared(smh);

    const int tid = threadIdx.x;
    const int lane = tid & 31;
    const int wid = tid >> 5;
    const int wm = wid >> 2;    // 0..1
    const int wn = wid & 3;     // 0..3
    const int m0 = blockIdx.y * BM;
    const int n0 = blockIdx.x * BN;

    const __half* gsrc[4];
    gsrc[0] = Ah + (long)m0 * K;
    gsrc[1] = Al + (long)m0 * K;
    gsrc[2] = Bh + (long)n0 * K;
    gsrc[3] = Bl + (long)n0 * K;

    const int r0 = tid >> 2;        // 0..63
    const int c0 = tid & 3;         // 16B chunk index within 64B row

    auto load_stage = [&](int stage, int k0) {
        unsigned sbase = smem_base + stage * 4 * TILEB;
#pragma unroll
        for (int a = 0; a < 4; a++) {
            if (PASSES == 2 && a == 1) continue;   // Al never used
#pragma unroll
            for (int t = 0; t < 2; t++) {
                int row = r0 + t * 64;
                const __half* g = gsrc[a] + (long)row * K + k0 + c0 * 8;
                unsigned s = sbase + a * TILEB + (row * SSTRIDE + c0 * 8) * 2;
                asm volatile("cp.async.ca.shared.global [%0], [%1], 16;"
                             :: "r"(s), "l"(g));
            }
        }
    };

    float acc[4][4][4];
#pragma unroll
    for (int i = 0; i < 4; i++)
#pragma unroll
        for (int j = 0; j < 4; j++)
#pragma unroll
            for (int r = 0; r < 4; r++) acc[i][j][r] = 0.f;

    const int nk = K / BKc;
    load_stage(0, 0);
    asm volatile("cp.async.commit_group;");
    load_stage(1, BKc);
    asm volatile("cp.async.commit_group;");

    for (int kc = 0; kc < nk; kc++) {
        int stage = kc & 1;
        asm volatile("cp.async.wait_group 1;");
        __syncthreads();

        unsigned sbase = smem_base + stage * 4 * TILEB;
        unsigned uAh = sbase;
        unsigned uAl = sbase + TILEB;
        unsigned uBh = sbase + 2 * TILEB;
        unsigned uBl = sbase + 3 * TILEB;

#pragma unroll
        for (int ks = 0; ks < 2; ks++) {
            const int kcol = ks * 16 + (lane >> 4) * 8;
            uint32_t afh[4][4], afl[4][4];
#pragma unroll
            for (int mi = 0; mi < 4; mi++) {
                int arow = wm * 64 + mi * 16 + (lane & 15);
                unsigned off = (arow * SSTRIDE + kcol) * 2;
                LDMX4(afh[mi][0], afh[mi][1], afh[mi][2], afh[mi][3], uAh + off);
                if (PASSES == 3) {
                    LDMX4(afl[mi][0], afl[mi][1], afl[mi][2], afl[mi][3], uAl + off);
                }
            }
            uint32_t bfh[4][2], bfl[4][2];
#pragma unroll
            for (int p = 0; p < 2; p++) {
                int brow = wn * 32 + p * 16 + (lane & 15);
                unsigned off = (brow * SSTRIDE + kcol) * 2;
                uint32_t t0, t1, t2, t3;
                LDMX4(t0, t1, t2, t3, uBh + off);
                bfh[p * 2][0] = t0; bfh[p * 2][1] = t2;
                bfh[p * 2 + 1][0] = t1; bfh[p * 2 + 1][1] = t3;
                LDMX4(t0, t1, t2, t3, uBl + off);
                bfl[p * 2][0] = t0; bfl[p * 2][1] = t2;
                bfl[p * 2 + 1][0] = t1; bfl[p * 2 + 1][1] = t3;
            }
#pragma unroll
            for (int mi = 0; mi < 4; mi++)
#pragma unroll
                for (int nj = 0; nj < 4; nj++) {
                    MMA16816(acc[mi][nj], afh[mi], bfh[nj][0], bfh[nj][1]);
                    MMA16816(acc[mi][nj], afh[mi], bfl[nj][0], bfl[nj][1]);
                    if (PASSES == 3) {
                        MMA16816(acc[mi][nj], afl[mi], bfh[nj][0], bfh[nj][1]);
                    }
                }
        }
        __syncthreads();
        int knext = (kc + 2) * BKc;
        if (knext < K) load_stage(stage, knext);
        asm volatile("cp.async.commit_group;");
    }

    // Epilogue
    const int lr = lane >> 2;
    const int lc = (lane & 3) * 2;
#pragma unroll
    for (int mi = 0; mi < 4; mi++) {
        int rbase = m0 + wm * 64 + mi * 16;
#pragma unroll
        for (int hf = 0; hf < 2; hf++) {
            int row = rbase + lr + hf * 8;
            float* dst;
            if (MODE == 0) {
                dst = C + (long)row * N + n0;
            } else {
                int b = row >> 11;
                int s = row & 2047;
                if (n0 < NH_ * HD_) {
                    int h = n0 >> 7;
                    dst = g_Q + (((long)(b * NH_ + h) * S_ + s) << 7);
                } else if (n0 < NH_ * HD_ + NKV_ * HD_) {
                    int h = (n0 - NH_ * HD_) >> 7;
                    dst = g_K + (((long)(b * NKV_ + h) * S_ + s) << 7);
                } else {
                    int h = (n0 - NH_ * HD_ - NKV_ * HD_) >> 7;
                    dst = g_V + (((long)(b * NKV_ + h) * S_ + s) << 7);
                }
            }
#pragma unroll
            for (int nj = 0; nj < 4; nj++) {
                int col = wn * 32 + nj * 8 + lc;
                float2 v = make_float2(acc[mi][nj][hf * 2 + 0],
                                       acc[mi][nj][hf * 2 + 1]);
                *(float2*)(dst + col) = v;
            }
        }
    }
}

// ---------------------------------------------------------------------------
// RoPE + split-fp16 convert
// ---------------------------------------------------------------------------
#define QPAIRS (B_ * NH_ * S_ * 64)
#define KPAIRS (B_ * NKV_ * S_ * 64)

__device__ __forceinline__ void split2w(float v, __half* ph, __half* pl, long off)
{
    __half h = __float2half_rn(v);
    ph[off] = h;
    pl[off] = __float2half_rn(v - __half2float(h));
}

__global__ __launch_bounds__(256) void rope_conv_kernel(
    const float* __restrict__ cosb, const float* __restrict__ sinb)
{
    int idx = blockIdx.x * 256 + threadIdx.x;
    if (idx < QPAIRS) {
        int d = idx & 63;
        int s = (idx >> 6) & 2047;
        int h = (idx >> 17) & 31;
        int b = idx >> 22;
        long base = ((long)(b * NH_ + h) * S_ + s) << 7;
        float c  = cosb[((long)(b * S_ + s) << 7) + d];
        float sn = sinb[((long)(b * S_ + s) << 7) + d];
        float x1 = g_Q[base + d];
        float x2 = g_Q[base + d + 64];
        split2w(x1 * c - x2 * sn, g_Qh, g_Ql, base + d);
        split2w(x2 * c + x1 * sn, g_Qh, g_Ql, base + d + 64);
    } else if (idx < QPAIRS + KPAIRS) {
        int i2 = idx - QPAIRS;
        int d = i2 & 63;
        int s = (i2 >> 6) & 2047;
        int h = (i2 >> 17) & 7;
        int b = i2 >> 20;
        long base = ((long)(b * NKV_ + h) * S_ + s) << 7;
        float c  = cosb[((long)(b * S_ + s) << 7) + d];
        float sn = sinb[((long)(b * S_ + s) << 7) + d];
        float x1 = g_K[base + d];
        float x2 = g_K[base + d + 64];
        split2w(x1 * c - x2 * sn, g_Kh, g_Kl, base + d);
        split2w(x2 * c + x1 * sn, g_Kh, g_Kl, base + d + 64);
    } else if (idx < QPAIRS + 2 * KPAIRS) {
        int i3 = idx - QPAIRS - KPAIRS;
        int d = i3 & 63;
        int s = (i3 >> 6) & 2047;
        int h = (i3 >> 17) & 7;
        int b = i3 >> 20;
        long base = ((long)(b * NKV_ + h) * S_ + s) << 7;
        split2w(g_V[base + d],      g_Vh, g_Vl, base + d);
        split2w(g_V[base + d + 64], g_Vh, g_Vl, base + d + 64);
    }
}

// ---------------------------------------------------------------------------
// FFMA-only exp2 (no MUFU). x <= 0 expected; rel err ~2e-5.
// ---------------------------------------------------------------------------
__device__ __forceinline__ float exp2p(float x)
{
    x = fmaxf(x, -120.f);
    float fl = floorf(x);
    float f = x - fl;
    float p = 1.5403530393381606e-4f;
    p = fmaf(p, f, 1.3333558146428443e-3f);
    p = fmaf(p, f, 9.6181291076284770e-3f);
    p = fmaf(p, f, 5.5504108664821580e-2f);
    p = fmaf(p, f, 2.4022650695910070e-1f);
    p = fmaf(p, f, 6.9314718055994531e-1f);
    p = fmaf(p, f, 1.0f);
    return __int_as_float(__float_as_int(p) + (((int)fl) << 23));
}

// ---------------------------------------------------------------------------
// Tensor-core causal flash attention (R4-proven), epilogue writes hi only.
// ---------------------------------------------------------------------------
#define ASTR 136
#define QH_B  0
#define QL_B  (128 * ASTR * 2)
#define STG_B (2 * 128 * ASTR * 2)
#define AKH_B 0
#define AKL_B (64 * ASTR * 2)
#define AVH_B (2 * 64 * ASTR * 2)
#define AVL_B (3 * 64 * ASTR * 2)
#define STG_SZB (4 * 64 * ASTR * 2)
#define ATT_SMEM (STG_B + 2 * STG_SZB)

__global__ __launch_bounds__(256, 1) void attn_mma_kernel()
{
    extern __shared__ __half sm[];
    const unsigned sbase = (unsigned)__cvta_generic_to_shared(sm);
    const int tid = threadIdx.x;
    const int lane = tid & 31;
    const int w = tid >> 5;
    const int qt = gridDim.x - 1 - blockIdx.x;
    const int bh = blockIdx.y;
    const int b = bh >> 5;
    const int h = bh & 31;
    const int hk = h >> 2;

    const __half* Qhp = g_Qh + ((long)(b * NH_ + h) * S_ << 7);
    const __half* Qlp = g_Ql + ((long)(b * NH_ + h) * S_ << 7);
    const __half* Khp = g_Kh + ((long)(b * NKV_ + hk) * S_ << 7);
    const __half* Klp = g_Kl + ((long)(b * NKV_ + hk) * S_ << 7);
    const __half* Vhp = g_Vh + ((long)(b * NKV_ + hk) * S_ << 7);
    const __half* Vlp = g_Vl + ((long)(b * NKV_ + hk) * S_ << 7);

    const int ktmax = 2 * qt + 1;
    const int rr = tid >> 4;
    const int cc = (tid & 15) * 8;

    auto cpa = [&](unsigned sboff, const __half* g) {
        asm volatile("cp.async.ca.shared.global [%0], [%1], 16;"
                     :: "r"(sbase + sboff), "l"(g));
    };
    auto load_kv = [&](int kt) {
        unsigned st = STG_B + (kt & 1) * STG_SZB;
        const __half* kb = Khp + (long)kt * 64 * 128;
        const __half* lb = Klp + (long)kt * 64 * 128;
        const __half* vb = Vhp + (long)kt * 64 * 128;
        const __half* wb = Vlp + (long)kt * 64 * 128;
#pragma unroll
        for (int it = 0; it < 4; it++) {
            int row = rr + it * 16;
            unsigned ro = (row * ASTR) * 2 + cc * 2;
            cpa(st + AKH_B + ro, kb + row * 128 + cc);
            cpa(st + AKL_B + ro, lb + row * 128 + cc);
            cpa(st + AVH_B + ro, vb + row * 128 + cc);
            cpa(st + AVL_B + ro, wb + row * 128 + cc);
        }
    };

    {
#pragma unroll
        for (int it = 0; it < 8; it++) {
            int row = rr + it * 16;
            unsigned ro = (row * ASTR) * 2 + cc * 2;
            cpa(QH_B + ro, Qhp + (long)(qt * 128 + row) * 128 + cc);
            cpa(QL_B + ro, Qlp + (long)(qt * 128 + row) * 128 + cc);
        }
        load_kv(0);
    }
    asm volatile("cp.async.commit_group;");
    load_kv(1);
    asm volatile("cp.async.commit_group;");

    float oacc[16][4];
#pragma unroll
    for (int t = 0; t < 16; t++)
#pragma unroll
        for (int e = 0; e < 4; e++) oacc[t][e] = 0.f;
    float mrow[2] = {-1e30f, -1e30f};
    float lrow[2] = {0.f, 0.f};

    const int qrow0 = qt * 128 + w * 16 + (lane >> 2);
    const float SL = SCALING * LOG2E;

    for (int kt = 0; kt <= ktmax; kt++) {
        asm volatile("cp.async.wait_group 1;");
        __syncthreads();

        unsigned st = sbase + STG_B + (kt & 1) * STG_SZB;

        float sacc[8][4];
#pragma unroll
        for (int j = 0; j < 8; j++)
#pragma unroll
            for (int e = 0; e < 4; e++) sacc[j][e] = 0.f;

#pragma unroll
        for (int ks = 0; ks < 8; ks++) {
            const int kcol = ks * 16 + (lane >> 4) * 8;
            unsigned aoff = ((w * 16 + (lane & 15)) * ASTR + kcol) * 2;
            uint32_t ah[4], al[4];
            LDMX4(ah[0], ah[1], ah[2], ah[3], sbase + QH_B + aoff);
            LDMX4(al[0], al[1], al[2], al[3], sbase + QL_B + aoff);
#pragma unroll
            for (int p = 0; p < 4; p++) {
                unsigned boff = ((p * 16 + (lane & 15)) * ASTR + kcol) * 2;
                uint32_t t0, t1, t2, t3, u0, u1, u2, u3;
                LDMX4(t0, t1, t2, t3, st + AKH_B + boff);
                LDMX4(u0, u1, u2, u3, st + AKL_B + boff);
                MMA16816(sacc[2 * p],     ah, t0, t2);
                MMA16816(sacc[2 * p],     al, t0, t2);
                MMA16816(sacc[2 * p],     ah, u0, u2);
                MMA16816(sacc[2 * p + 1], ah, t1, t3);
                MMA16816(sacc[2 * p + 1], al, t1, t3);
                MMA16816(sacc[2 * p + 1], ah, u1, u3);
            }
        }

        const bool diag = (kt >= 2 * qt);
        float rmax[2] = {-1e30f, -1e30f};
#pragma unroll
        for (int j = 0; j < 8; j++)
#pragma unroll
            for (int e = 0; e < 4; e++) {
                float v = sacc[j][e] * SL;
                if (diag) {
                    int col = kt * 64 + j * 8 + (lane & 3) * 2 + (e & 1);
                    int row = qrow0 + (e >> 1) * 8;
                    if (col > row) v = -1e30f;
                }
                sacc[j][e] = v;
                rmax[e >> 1] = fmaxf(rmax[e >> 1], v);
            }
#pragma unroll
        for (int r = 0; r < 2; r++) {
            rmax[r] = fmaxf(rmax[r], __shfl_xor_sync(0xffffffffu, rmax[r], 1));
            rmax[r] = fmaxf(rmax[r], __shfl_xor_sync(0xffffffffu, rmax[r], 2));
        }
        float mn0 = fmaxf(mrow[0], rmax[0]);
        float mn1 = fmaxf(mrow[1], rmax[1]);
        float al0 = exp2p(mrow[0] - mn0);
        float al1 = exp2p(mrow[1] - mn1);
        mrow[0] = mn0; mrow[1] = mn1;

        uint32_t ph[8][2], pl[8][2];
        float ls0 = 0.f, ls1 = 0.f;
#pragma unroll
        for (int j = 0; j < 8; j++) {
            float p0 = exp2p(sacc[j][0] - mn0);
            float p1 = exp2p(sacc[j][1] - mn0);
            float p2 = exp2p(sacc[j][2] - mn1);
            float p3 = exp2p(sacc[j][3] - mn1);
            ls0 += p0 + p1;
            ls1 += p2 + p3;
            __half2 h01 = __floats2half2_rn(p0, p1);
            __half2 h23 = __floats2half2_rn(p2, p3);
            ph[j][0] = *(uint32_t*)&h01;
            ph[j][1] = *(uint32_t*)&h23;
            float2 f01 = __half22float2(h01);
            float2 f23 = __half22float2(h23);
            __half2 l01 = __floats2half2_rn(p0 - f01.x, p1 - f01.y);
            __half2 l23 = __floats2half2_rn(p2 - f23.x, p3 - f23.y);
            pl[j][0] = *(uint32_t*)&l01;
            pl[j][1] = *(uint32_t*)&l23;
        }
        ls0 += __shfl_xor_sync(0xffffffffu, ls0, 1);
        ls0 += __shfl_xor_sync(0xffffffffu, ls0, 2);
        ls1 += __shfl_xor_sync(0xffffffffu, ls1, 1);
        ls1 += __shfl_xor_sync(0xffffffffu, ls1, 2);
        lrow[0] = lrow[0] * al0 + ls0;
        lrow[1] = lrow[1] * al1 + ls1;
#pragma unroll
        for (int t = 0; t < 16; t++) {
            oacc[t][0] *= al0; oacc[t][1] *= al0;
            oacc[t][2] *= al1; oacc[t][3] *= al1;
        }

#pragma unroll
        for (int dk = 0; dk < 4; dk++) {
            uint32_t aPh[4] = {ph[2 * dk][0], ph[2 * dk][1],
                               ph[2 * dk + 1][0], ph[2 * dk + 1][1]};
            uint32_t aPl[4] = {pl[2 * dk][0], pl[2 * dk][1],
                               pl[2 * dk + 1][0], pl[2 * dk + 1][1]};
#pragma unroll
            for (int np = 0; np < 8; np++) {
                unsigned vo = ((dk * 16 + (lane & 15)) * ASTR +
                               np * 16 + (lane >> 4) * 8) * 2;
                uint32_t t0, t1, t2, t3, u0, u1, u2, u3;
                LDMX4T(t0, t1, t2, t3, st + AVH_B + vo);
                LDMX4T(u0, u1, u2, u3, st + AVL_B + vo);
                MMA16816(oacc[2 * np],     aPh, t0, t1);
                MMA16816(oacc[2 * np],     aPh, u0, u1);
                MMA16816(oacc[2 * np],     aPl, t0, t1);
                MMA16816(oacc[2 * np + 1], aPh, t2, t3);
                MMA16816(oacc[2 * np + 1], aPh, u2, u3);
                MMA16816(oacc[2 * np + 1], aPl, t2, t3);
            }
        }

        __syncthreads();
        if (kt + 2 <= ktmax) load_kv(kt + 2);
        asm volatile("cp.async.commit_group;");
    }

    // finalize: write hi-only split O in [b*s][h*d] layout
    float inv0 = 1.f / lrow[0];
    float inv1 = 1.f / lrow[1];
    long row0 = (long)(b * S_ + qt * 128 + w * 16 + (lane >> 2));
    long cbase = (long)h * 128 + (lane & 3) * 2;
#pragma unroll
    for (int t = 0; t < 16; t++) {
        long off0 = row0 * (NH_ * HD_) + cbase + t * 8;
        long off1 = off0 + 8L * (NH_ * HD_);
        float v0 = oacc[t][0] * inv0, v1 = oacc[t][1] * inv0;
        float v2 = oacc[t][2] * inv1, v3 = oacc[t][3] * inv1;
        __half2 h0 = __floats2half2_rn(v0, v1);
        __half2 h1 = __floats2half2_rn(v2, v3);
        *(uint32_t*)(g_Ohi + off0) = *(uint32_t*)&h0;
        *(uint32_t*)(g_Ohi + off1) = *(uint32_t*)&h1;
    }
}

// ---------------------------------------------------------------------------
extern "C" void kernel_launch(void* const* d_in, const int* in_sizes, int n_in,
                              void* d_out, int out_size)
{
    const float* hidden = (const float*)d_in[0];
    const float* cosb   = (const float*)d_in[1];
    const float* sinb   = (const float*)d_in[2];
    const float* Wq = (const float*)d_in[4];
    const float* Wk = (const float*)d_in[5];
    const float* Wv = (const float*)d_in[6];
    const float* Wo = (const float*)d_in[7];
    float* out = (float*)d_out;

    __half *pAhi, *pAlo, *pWhi, *pWlo, *pWOhi, *pWOlo, *pOhi, *pOlo;
    cudaGetSymbolAddress((void**)&pAhi, g_Ahi);
    cudaGetSymbolAddress((void**)&pAlo, g_Alo);
    cudaGetSymbolAddress((void**)&pWhi, g_Whi);
    cudaGetSymbolAddress((void**)&pWlo, g_Wlo);
    cudaGetSymbolAddress((void**)&pWOhi, g_WOhi);
    cudaGetSymbolAddress((void**)&pWOlo, g_WOlo);
    cudaGetSymbolAddress((void**)&pOhi, g_Ohi);
    cudaGetSymbolAddress((void**)&pOlo, g_Olo);

    cudaFuncSetAttribute((const void*)hgemm<0, 2>, cudaFuncAttributeMaxDynamicSharedMemorySize, HGEMM_SMEM);
    cudaFuncSetAttribute((const void*)hgemm<1, 2>, cudaFuncAttributeMaxDynamicSharedMemorySize, HGEMM_SMEM);
    cudaFuncSetAttribute(attn_mma_kernel, cudaFuncAttributeMaxDynamicSharedMemorySize, ATT_SMEM);

    // 1) fp16 splits of activations and weights
    int n4;
    n4 = MTOK * HID_ / 4;
    split_kernel<<<(n4 + 255) / 256, 256>>>(hidden, pAhi, pAlo, n4);
    n4 = NH_ * HD_ * HID_ / 4;
    split_kernel<<<(n4 + 255) / 256, 256>>>(Wq, pWhi, pWlo, n4);
    n4 = NKV_ * HD_ * HID_ / 4;
    split_kernel<<<(n4 + 255) / 256, 256>>>(Wk, pWhi + (long)NH_ * HD_ * HID_,
                                            pWlo + (long)NH_ * HD_ * HID_, n4);
    split_kernel<<<(n4 + 255) / 256, 256>>>(Wv, pWhi + (long)(NH_ + NKV_) * HD_ * HID_,
                                            pWlo + (long)(NH_ + NKV_) * HD_ * HID_, n4);
    n4 = HID_ * HID_ / 4;
    split_kernel<<<(n4 + 255) / 256, 256>>>(Wo, pWOhi, pWOlo, n4);

    // 2) QKV projection (tensor cores, 2-pass: Ah*(Wh+Wl)) + scatter
    hgemm<1, 2><<<dim3(NQKV / BN, MTOK / BM), 256, HGEMM_SMEM>>>(
        pAhi, pAlo, pWhi, pWlo, nullptr, MTOK, NQKV, HID_);

    // 3) RoPE + split-fp16 conversion of Q, K, V
    int total = QPAIRS + 2 * KPAIRS;
    rope_conv_kernel<<<(total + 255) / 256, 256>>>(cosb, sinb);

    // 4) Tensor-core causal flash attention (3-pass, unchanged)
    attn_mma_kernel<<<dim3(S_ / 128, B_ * NH_), 256, ATT_SMEM>>>();

    // 5) Output projection (tensor cores, 2-pass: Ohi*(WOhi+WOlo))
    hgemm<0, 2><<<dim3(HID_ / BN, MTOK / BM), 256, HGEMM_SMEM>>>(
        pOhi, pOlo, pWOhi, pWOlo, out, MTOK, HID_, HID_);
}

// round 14
// speedup vs baseline: 1.9247x; 1.2258x over previous
#include <cuda_runtime.h>
#include <cuda_fp16.h>
#include <cstdint>
#include <math.h>

// Problem constants
#define B_    2
#define S_    2048
#define HID_  4096
#define NH_   32
#define NKV_  8
#define HD_   128
#define MTOK  (B_ * S_)                    // 4096
#define NQKV  (NH_ * HD_ + 2 * NKV_ * HD_) // 6144
#define SCALING 0.08838834764831845f
#define LOG2E  1.4426950408889634f

// fp32 scratch (QKV projection output, pre-rope)
__device__ float g_Q[B_ * NH_ * S_ * HD_];
__device__ float g_K[B_ * NKV_ * S_ * HD_];
__device__ float g_V[B_ * NKV_ * S_ * HD_];

// fp16 post-rope QKV for attention (Q hi only; K/V split)
__device__ __half g_Qh[B_ * NH_ * S_ * HD_];
__device__ __half g_Kh[B_ * NKV_ * S_ * HD_];
__device__ __half g_Kl[B_ * NKV_ * S_ * HD_];
__device__ __half g_Vh[B_ * NKV_ * S_ * HD_];
__device__ __half g_Vl[B_ * NKV_ * S_ * HD_];

// fp16 split scratch for projections
__device__ __half g_Ahi[MTOK * HID_];
__device__ __half g_Alo[MTOK * HID_];
__device__ __half g_Whi[NQKV * HID_];
__device__ __half g_Wlo[NQKV * HID_];
__device__ __half g_WOhi[HID_ * HID_];
__device__ __half g_WOlo[HID_ * HID_];
__device__ __half g_Ohi[MTOK * HID_];   // attention out, hi

// ---------------------------------------------------------------------------
__global__ __launch_bounds__(256) void split_kernel(
    const float* __restrict__ src, __half* __restrict__ hi,
    __half* __restrict__ lo, int n4)
{
    int i = blockIdx.x * 256 + threadIdx.x;
    if (i >= n4) return;
    float4 v = ((const float4*)src)[i];
    __half h0 = __float2half_rn(v.x);
    __half h1 = __float2half_rn(v.y);
    __half h2 = __float2half_rn(v.z);
    __half h3 = __float2half_rn(v.w);
    __half l0 = __float2half_rn(v.x - __half2float(h0));
    __half l1 = __float2half_rn(v.y - __half2float(h1));
    __half l2 = __float2half_rn(v.z - __half2float(h2));
    __half l3 = __float2half_rn(v.w - __half2float(h3));
    ((__half2*)hi)[2 * i + 0] = __halves2half2(h0, h1);
    ((__half2*)hi)[2 * i + 1] = __halves2half2(h2, h3);
    ((__half2*)lo)[2 * i + 0] = __halves2half2(l0, l1);
    ((__half2*)lo)[2 * i + 1] = __halves2half2(l2, l3);
}

// ---------------------------------------------------------------------------
// Split-fp16 tensor-core GEMM: C[M,N] = A[M,K] @ B[N,K]^T  (fp32 result)
// 128x128x32 block tile, 256 threads (8 warps, 2x4), warp tile 64x32,
// mma.sync.m16n8k16, cp.async double buffering.
// PASSES=3: AhBh+AhBl+AlBh.  PASSES=2: AhBh+AhBl.  PASSES=1: AhBh only.
// MODE 0: plain store; MODE 1: QKV scatter into g_Q/g_K/g_V.
// ---------------------------------------------------------------------------
#define BM 128
#define BN 128
#define BKc 32
#define SSTRIDE 40                     // fp16 elems per smem row (conflict-free)
#define TILEB (128 * SSTRIDE * 2)      // bytes per (array, stage) tile = 10240
#define HGEMM_SMEM (2 * 4 * TILEB)     // 81920 bytes

#define LDMX4(R0, R1, R2, R3, ADDR)                                          \
    asm volatile("ldmatrix.sync.aligned.m8n8.x4.shared.b16 {%0,%1,%2,%3}, [%4];" \
                 : "=r"(R0), "=r"(R1), "=r"(R2), "=r"(R3) : "r"(ADDR))

#define LDMX4T(R0, R1, R2, R3, ADDR)                                         \
    asm volatile("ldmatrix.sync.aligned.m8n8.x4.trans.shared.b16 {%0,%1,%2,%3}, [%4];" \
                 : "=r"(R0), "=r"(R1), "=r"(R2), "=r"(R3) : "r"(ADDR))

#define MMA16816(C, A, B0, B1)                                               \
    asm volatile("mma.sync.aligned.m16n8k16.row.col.f32.f16.f16.f32 "        \
                 "{%0,%1,%2,%3}, {%4,%5,%6,%7}, {%8,%9}, {%0,%1,%2,%3};"     \
                 : "+f"(C[0]), "+f"(C[1]), "+f"(C[2]), "+f"(C[3])            \
                 : "r"(A[0]), "r"(A[1]), "r"(A[2]), "r"(A[3]), "r"(B0), "r"(B1))

template <int MODE, int PASSES>
__global__ __launch_bounds__(256) void hgemm(
    const __half* __restrict__ Ah, const __half* __restrict__ Al,
    const __half* __restrict__ Bh, const __half* __restrict__ Bl,
    float* __restrict__ C, int M, int N, int K)
{
    extern __shared__ __half smh[];
    const unsigned smem_base = (unsigned)__cvta_generic_to_shared(smh);

    const int tid = threadIdx.x;
    const int lane = tid & 31;
    const int wid = tid >> 5;
    const int wm = wid >> 2;    // 0..1
    const int wn = wid & 3;     // 0..3
    const int m0 = blockIdx.y * BM;
    const int n0 = blockIdx.x * BN;

    const __half* gsrc[4];
    gsrc[0] = Ah + (long)m0 * K;
    gsrc[1] = Al + (long)m0 * K;
    gsrc[2] = Bh + (long)n0 * K;
    gsrc[3] = Bl + (long)n0 * K;

    const int r0 = tid >> 2;        // 0..63
    const int c0 = tid & 3;         // 16B chunk index within 64B row

    auto load_stage = [&](int stage, int k0) {
        unsigned sbase = smem_base + stage * 4 * TILEB;
#pragma unroll
        for (int a = 0; a < 4; a++) {
            if (PASSES <= 2 && a == 1) continue;   // Al never used
            if (PASSES == 1 && a == 3) continue;   // Bl never used
#pragma unroll
            for (int t = 0; t < 2; t++) {
                int row = r0 + t * 64;
                const __half* g = gsrc[a] + (long)row * K + k0 + c0 * 8;
                unsigned s = sbase + a * TILEB + (row * SSTRIDE + c0 * 8) * 2;
                asm volatile("cp.async.ca.shared.global [%0], [%1], 16;"
                             :: "r"(s), "l"(g));
            }
        }
    };

    float acc[4][4][4];
#pragma unroll
    for (int i = 0; i < 4; i++)
#pragma unroll
        for (int j = 0; j < 4; j++)
#pragma unroll
            for (int r = 0; r < 4; r++) acc[i][j][r] = 0.f;

    const int nk = K / BKc;
    load_stage(0, 0);
    asm volatile("cp.async.commit_group;");
    load_stage(1, BKc);
    asm volatile("cp.async.commit_group;");

    for (int kc = 0; kc < nk; kc++) {
        int stage = kc & 1;
        asm volatile("cp.async.wait_group 1;");
        __syncthreads();

        unsigned sbase = smem_base + stage * 4 * TILEB;
        unsigned uAh = sbase;
        unsigned uAl = sbase + TILEB;
        unsigned uBh = sbase + 2 * TILEB;
        unsigned uBl = sbase + 3 * TILEB;

#pragma unroll
        for (int ks = 0; ks < 2; ks++) {
            const int kcol = ks * 16 + (lane >> 4) * 8;
            uint32_t afh[4][4], afl[4][4];
#pragma unroll
            for (int mi = 0; mi < 4; mi++) {
                int arow = wm * 64 + mi * 16 + (lane & 15);
                unsigned off = (arow * SSTRIDE + kcol) * 2;
                LDMX4(afh[mi][0], afh[mi][1], afh[mi][2], afh[mi][3], uAh + off);
                if (PASSES == 3) {
                    LDMX4(afl[mi][0], afl[mi][1], afl[mi][2], afl[mi][3], uAl + off);
                }
            }
            uint32_t bfh[4][2], bfl[4][2];
#pragma unroll
            for (int p = 0; p < 2; p++) {
                int brow = wn * 32 + p * 16 + (lane & 15);
                unsigned off = (brow * SSTRIDE + kcol) * 2;
                uint32_t t0, t1, t2, t3;
                LDMX4(t0, t1, t2, t3, uBh + off);
                bfh[p * 2][0] = t0; bfh[p * 2][1] = t2;
                bfh[p * 2 + 1][0] = t1; bfh[p * 2 + 1][1] = t3;
                if (PASSES >= 2) {
                    LDMX4(t0, t1, t2, t3, uBl + off);
                    bfl[p * 2][0] = t0; bfl[p * 2][1] = t2;
                    bfl[p * 2 + 1][0] = t1; bfl[p * 2 + 1][1] = t3;
                }
            }
#pragma unroll
            for (int mi = 0; mi < 4; mi++)
#pragma unroll
                for (int nj = 0; nj < 4; nj++) {
                    MMA16816(acc[mi][nj], afh[mi], bfh[nj][0], bfh[nj][1]);
                    if (PASSES >= 2) {
                        MMA16816(acc[mi][nj], afh[mi], bfl[nj][0], bfl[nj][1]);
                    }
                    if (PASSES == 3) {
                        MMA16816(acc[mi][nj], afl[mi], bfh[nj][0], bfh[nj][1]);
                    }
                }
        }
        __syncthreads();
        int knext = (kc + 2) * BKc;
        if (knext < K) load_stage(stage, knext);
        asm volatile("cp.async.commit_group;");
    }

    // Epilogue
    const int lr = lane >> 2;
    const int lc = (lane & 3) * 2;
#pragma unroll
    for (int mi = 0; mi < 4; mi++) {
        int rbase = m0 + wm * 64 + mi * 16;
#pragma unroll
        for (int hf = 0; hf < 2; hf++) {
            int row = rbase + lr + hf * 8;
            float* dst;
            if (MODE == 0) {
                dst = C + (long)row * N + n0;
            } else {
                int b = row >> 11;
                int s = row & 2047;
                if (n0 < NH_ * HD_) {
                    int h = n0 >> 7;
                    dst = g_Q + (((long)(b * NH_ + h) * S_ + s) << 7);
                } else if (n0 < NH_ * HD_ + NKV_ * HD_) {
                    int h = (n0 - NH_ * HD_) >> 7;
                    dst = g_K + (((long)(b * NKV_ + h) * S_ + s) << 7);
                } else {
                    int h = (n0 - NH_ * HD_ - NKV_ * HD_) >> 7;
                    dst = g_V + (((long)(b * NKV_ + h) * S_ + s) << 7);
                }
            }
#pragma unroll
            for (int nj = 0; nj < 4; nj++) {
                int col = wn * 32 + nj * 8 + lc;
                float2 v = make_float2(acc[mi][nj][hf * 2 + 0],
                                       acc[mi][nj][hf * 2 + 1]);
                *(float2*)(dst + col) = v;
            }
        }
    }
}

// ---------------------------------------------------------------------------
// RoPE + convert: Q -> hi only; K -> split; V -> split
// ---------------------------------------------------------------------------
#define QPAIRS (B_ * NH_ * S_ * 64)
#define KPAIRS (B_ * NKV_ * S_ * 64)

__device__ __forceinline__ void split2w(float v, __half* ph, __half* pl, long off)
{
    __half h = __float2half_rn(v);
    ph[off] = h;
    pl[off] = __float2half_rn(v - __half2float(h));
}

__global__ __launch_bounds__(256) void rope_conv_kernel(
    const float* __restrict__ cosb, const float* __restrict__ sinb)
{
    int idx = blockIdx.x * 256 + threadIdx.x;
    if (idx < QPAIRS) {
        int d = idx & 63;
        int s = (idx >> 6) & 2047;
        int h = (idx >> 17) & 31;
        int b = idx >> 22;
        long base = ((long)(b * NH_ + h) * S_ + s) << 7;
        float c  = cosb[((long)(b * S_ + s) << 7) + d];
        float sn = sinb[((long)(b * S_ + s) << 7) + d];
        float x1 = g_Q[base + d];
        float x2 = g_Q[base + d + 64];
        g_Qh[base + d]      = __float2half_rn(x1 * c - x2 * sn);
        g_Qh[base + d + 64] = __float2half_rn(x2 * c + x1 * sn);
    } else if (idx < QPAIRS + KPAIRS) {
        int i2 = idx - QPAIRS;
        int d = i2 & 63;
        int s = (i2 >> 6) & 2047;
        int h = (i2 >> 17) & 7;
        int b = i2 >> 20;
        long base = ((long)(b * NKV_ + h) * S_ + s) << 7;
        float c  = cosb[((long)(b * S_ + s) << 7) + d];
        float sn = sinb[((long)(b * S_ + s) << 7) + d];
        float x1 = g_K[base + d];
        float x2 = g_K[base + d + 64];
        split2w(x1 * c - x2 * sn, g_Kh, g_Kl, base + d);
        split2w(x2 * c + x1 * sn, g_Kh, g_Kl, base + d + 64);
    } else if (idx < QPAIRS + 2 * KPAIRS) {
        int i3 = idx - QPAIRS - KPAIRS;
        int d = i3 & 63;
        int s = (i3 >> 6) & 2047;
        int h = (i3 >> 17) & 7;
        int b = i3 >> 20;
        long base = ((long)(b * NKV_ + h) * S_ + s) << 7;
        split2w(g_V[base + d],      g_Vh, g_Vl, base + d);
        split2w(g_V[base + d + 64], g_Vh, g_Vl, base + d + 64);
    }
}

// ---------------------------------------------------------------------------
// FFMA-only exp2 (no MUFU). x <= 0 expected; rel err ~2e-5.
// ---------------------------------------------------------------------------
__device__ __forceinline__ float exp2p(float x)
{
    x = fmaxf(x, -120.f);
    float fl = floorf(x);
    float f = x - fl;
    float p = 1.5403530393381606e-4f;
    p = fmaf(p, f, 1.3333558146428443e-3f);
    p = fmaf(p, f, 9.6181291076284770e-3f);
    p = fmaf(p, f, 5.5504108664821580e-2f);
    p = fmaf(p, f, 2.4022650695910070e-1f);
    p = fmaf(p, f, 6.9314718055994531e-1f);
    p = fmaf(p, f, 1.0f);
    return __int_as_float(__float_as_int(p) + (((int)fl) << 23));
}

// ---------------------------------------------------------------------------
// Tensor-core causal flash attention, 2-pass:
// QK = Qh*Kh + Qh*Kl ; PV = Ph*Vh + Ph*Vl.  Q hi only; P hi only.
// ---------------------------------------------------------------------------
#define ASTR 136
#define QH_B  0
#define STG_B (128 * ASTR * 2)            // 34816
#define AKH_B 0
#define AKL_B (64 * ASTR * 2)
#define AVH_B (2 * 64 * ASTR * 2)
#define AVL_B (3 * 64 * ASTR * 2)
#define STG_SZB (4 * 64 * ASTR * 2)       // 69632
#define ATT_SMEM (STG_B + 2 * STG_SZB)    // 174080

__global__ __launch_bounds__(256, 1) void attn_mma_kernel()
{
    extern __shared__ __half sm[];
    const unsigned sbase = (unsigned)__cvta_generic_to_shared(sm);
    const int tid = threadIdx.x;
    const int lane = tid & 31;
    const int w = tid >> 5;
    const int qt = gridDim.x - 1 - blockIdx.x;
    const int bh = blockIdx.y;
    const int b = bh >> 5;
    const int h = bh & 31;
    const int hk = h >> 2;

    const __half* Qhp = g_Qh + ((long)(b * NH_ + h) * S_ << 7);
    const __half* Khp = g_Kh + ((long)(b * NKV_ + hk) * S_ << 7);
    const __half* Klp = g_Kl + ((long)(b * NKV_ + hk) * S_ << 7);
    const __half* Vhp = g_Vh + ((long)(b * NKV_ + hk) * S_ << 7);
    const __half* Vlp = g_Vl + ((long)(b * NKV_ + hk) * S_ << 7);

    const int ktmax = 2 * qt + 1;
    const int rr = tid >> 4;
    const int cc = (tid & 15) * 8;

    auto cpa = [&](unsigned sboff, const __half* g) {
        asm volatile("cp.async.ca.shared.global [%0], [%1], 16;"
                     :: "r"(sbase + sboff), "l"(g));
    };
    auto load_kv = [&](int kt) {
        unsigned st = STG_B + (kt & 1) * STG_SZB;
        const __half* kb = Khp + (long)kt * 64 * 128;
        const __half* lb = Klp + (long)kt * 64 * 128;
        const __half* vb = Vhp + (long)kt * 64 * 128;
        const __half* wb = Vlp + (long)kt * 64 * 128;
#pragma unroll
        for (int it = 0; it < 4; it++) {
            int row = rr + it * 16;
            unsigned ro = (row * ASTR) * 2 + cc * 2;
            cpa(st + AKH_B + ro, kb + row * 128 + cc);
            cpa(st + AKL_B + ro, lb + row * 128 + cc);
            cpa(st + AVH_B + ro, vb + row * 128 + cc);
            cpa(st + AVL_B + ro, wb + row * 128 + cc);
        }
    };

    {
#pragma unroll
        for (int it = 0; it < 8; it++) {
            int row = rr + it * 16;
            unsigned ro = (row * ASTR) * 2 + cc * 2;
            cpa(QH_B + ro, Qhp + (long)(qt * 128 + row) * 128 + cc);
        }
        load_kv(0);
    }
    asm volatile("cp.async.commit_group;");
    load_kv(1);
    asm volatile("cp.async.commit_group;");

    float oacc[16][4];
#pragma unroll
    for (int t = 0; t < 16; t++)
#pragma unroll
        for (int e = 0; e < 4; e++) oacc[t][e] = 0.f;
    float mrow[2] = {-1e30f, -1e30f};
    float lrow[2] = {0.f, 0.f};

    const int qrow0 = qt * 128 + w * 16 + (lane >> 2);
    const float SL = SCALING * LOG2E;

    for (int kt = 0; kt <= ktmax; kt++) {
        asm volatile("cp.async.wait_group 1;");
        __syncthreads();

        unsigned st = sbase + STG_B + (kt & 1) * STG_SZB;

        float sacc[8][4];
#pragma unroll
        for (int j = 0; j < 8; j++)
#pragma unroll
            for (int e = 0; e < 4; e++) sacc[j][e] = 0.f;

#pragma unroll
        for (int ks = 0; ks < 8; ks++) {
            const int kcol = ks * 16 + (lane >> 4) * 8;
            unsigned aoff = ((w * 16 + (lane & 15)) * ASTR + kcol) * 2;
            uint32_t ah[4];
            LDMX4(ah[0], ah[1], ah[2], ah[3], sbase + QH_B + aoff);
#pragma unroll
            for (int p = 0; p < 4; p++) {
                unsigned boff = ((p * 16 + (lane & 15)) * ASTR + kcol) * 2;
                uint32_t t0, t1, t2, t3, u0, u1, u2, u3;
                LDMX4(t0, t1, t2, t3, st + AKH_B + boff);
                LDMX4(u0, u1, u2, u3, st + AKL_B + boff);
                MMA16816(sacc[2 * p],     ah, t0, t2);
                MMA16816(sacc[2 * p],     ah, u0, u2);
                MMA16816(sacc[2 * p + 1], ah, t1, t3);
                MMA16816(sacc[2 * p + 1], ah, u1, u3);
            }
        }

        const bool diag = (kt >= 2 * qt);
        float rmax[2] = {-1e30f, -1e30f};
#pragma unroll
        for (int j = 0; j < 8; j++)
#pragma unroll
            for (int e = 0; e < 4; e++) {
                float v = sacc[j][e] * SL;
                if (diag) {
                    int col = kt * 64 + j * 8 + (lane & 3) * 2 + (e & 1);
                    int row = qrow0 + (e >> 1) * 8;
                    if (col > row) v = -1e30f;
                }
                sacc[j][e] = v;
                rmax[e >> 1] = fmaxf(rmax[e >> 1], v);
            }
#pragma unroll
        for (int r = 0; r < 2; r++) {
            rmax[r] = fmaxf(rmax[r], __shfl_xor_sync(0xffffffffu, rmax[r], 1));
            rmax[r] = fmaxf(rmax[r], __shfl_xor_sync(0xffffffffu, rmax[r], 2));
        }
        float mn0 = fmaxf(mrow[0], rmax[0]);
        float mn1 = fmaxf(mrow[1], rmax[1]);
        float al0 = exp2p(mrow[0] - mn0);
        float al1 = exp2p(mrow[1] - mn1);
        mrow[0] = mn0; mrow[1] = mn1;

        uint32_t ph[8][2];
        float ls0 = 0.f, ls1 = 0.f;
#pragma unroll
        for (int j = 0; j < 8; j++) {
            float p0 = exp2p(sacc[j][0] - mn0);
            float p1 = exp2p(sacc[j][1] - mn0);
            float p2 = exp2p(sacc[j][2] - mn1);
            float p3 = exp2p(sacc[j][3] - mn1);
            ls0 += p0 + p1;
            ls1 += p2 + p3;
            __half2 h01 = __floats2half2_rn(p0, p1);
            __half2 h23 = __floats2half2_rn(p2, p3);
            ph[j][0] = *(uint32_t*)&h01;
            ph[j][1] = *(uint32_t*)&h23;
        }
        ls0 += __shfl_xor_sync(0xffffffffu, ls0, 1);
        ls0 += __shfl_xor_sync(0xffffffffu, ls0, 2);
        ls1 += __shfl_xor_sync(0xffffffffu, ls1, 1);
        ls1 += __shfl_xor_sync(0xffffffffu, ls1, 2);
        lrow[0] = lrow[0] * al0 + ls0;
        lrow[1] = lrow[1] * al1 + ls1;
#pragma unroll
        for (int t = 0; t < 16; t++) {
            oacc[t][0] *= al0; oacc[t][1] *= al0;
            oacc[t][2] *= al1; oacc[t][3] *= al1;
        }

#pragma unroll
        for (int dk = 0; dk < 4; dk++) {
            uint32_t aPh[4] = {ph[2 * dk][0], ph[2 * dk][1],
                               ph[2 * dk + 1][0], ph[2 * dk + 1][1]};
#pragma unroll
            for (int np = 0; np < 8; np++) {
                unsigned vo = ((dk * 16 + (lane & 15)) * ASTR +
                               np * 16 + (lane >> 4) * 8) * 2;
                uint32_t t0, t1, t2, t3, u0, u1, u2, u3;
                LDMX4T(t0, t1, t2, t3, st + AVH_B + vo);
                LDMX4T(u0, u1, u2, u3, st + AVL_B + vo);
                MMA16816(oacc[2 * np],     aPh, t0, t1);
                MMA16816(oacc[2 * np],     aPh, u0, u1);
                MMA16816(oacc[2 * np + 1], aPh, t2, t3);
                MMA16816(oacc[2 * np + 1], aPh, u2, u3);
            }
        }

        __syncthreads();
        if (kt + 2 <= ktmax) load_kv(kt + 2);
        asm volatile("cp.async.commit_group;");
    }

    // finalize: write hi-only O in [b*s][h*d] layout
    float inv0 = 1.f / lrow[0];
    float inv1 = 1.f / lrow[1];
    long row0 = (long)(b * S_ + qt * 128 + w * 16 + (lane >> 2));
    long cbase = (long)h * 128 + (lane & 3) * 2;
#pragma unroll
    for (int t = 0; t < 16; t++) {
        long off0 = row0 * (NH_ * HD_) + cbase + t * 8;
        long off1 = off0 + 8L * (NH_ * HD_);
        float v0 = oacc[t][0] * inv0, v1 = oacc[t][1] * inv0;
        float v2 = oacc[t][2] * inv1, v3 = oacc[t][3] * inv1;
        __half2 h0 = __floats2half2_rn(v0, v1);
        __half2 h1 = __floats2half2_rn(v2, v3);
        *(uint32_t*)(g_Ohi + off0) = *(uint32_t*)&h0;
        *(uint32_t*)(g_Ohi + off1) = *(uint32_t*)&h1;
    }
}

// ---------------------------------------------------------------------------
extern "C" void kernel_launch(void* const* d_in, const int* in_sizes, int n_in,
                              void* d_out, int out_size)
{
    const float* hidden = (const float*)d_in[0];
    const float* cosb   = (const float*)d_in[1];
    const float* sinb   = (const float*)d_in[2];
    const float* Wq = (const float*)d_in[4];
    const float* Wk = (const float*)d_in[5];
    const float* Wv = (const float*)d_in[6];
    const float* Wo = (const float*)d_in[7];
    float* out = (float*)d_out;

    __half *pAhi, *pAlo, *pWhi, *pWlo, *pWOhi, *pWOlo, *pOhi;
    cudaGetSymbolAddress((void**)&pAhi, g_Ahi);
    cudaGetSymbolAddress((void**)&pAlo, g_Alo);
    cudaGetSymbolAddress((void**)&pWhi, g_Whi);
    cudaGetSymbolAddress((void**)&pWlo, g_Wlo);
    cudaGetSymbolAddress((void**)&pWOhi, g_WOhi);
    cudaGetSymbolAddress((void**)&pWOlo, g_WOlo);
    cudaGetSymbolAddress((void**)&pOhi, g_Ohi);

    cudaFuncSetAttribute((const void*)hgemm<0, 1>, cudaFuncAttributeMaxDynamicSharedMemorySize, HGEMM_SMEM);
    cudaFuncSetAttribute((const void*)hgemm<1, 2>, cudaFuncAttributeMaxDynamicSharedMemorySize, HGEMM_SMEM);
    cudaFuncSetAttribute(attn_mma_kernel, cudaFuncAttributeMaxDynamicSharedMemorySize, ATT_SMEM);

    // 1) fp16 splits of activations and weights
    int n4;
    n4 = MTOK * HID_ / 4;
    split_kernel<<<(n4 + 255) / 256, 256>>>(hidden, pAhi, pAlo, n4);
    n4 = NH_ * HD_ * HID_ / 4;
    split_kernel<<<(n4 + 255) / 256, 256>>>(Wq, pWhi, pWlo, n4);
    n4 = NKV_ * HD_ * HID_ / 4;
    split_kernel<<<(n4 + 255) / 256, 256>>>(Wk, pWhi + (long)NH_ * HD_ * HID_,
                                            pWlo + (long)NH_ * HD_ * HID_, n4);
    split_kernel<<<(n4 + 255) / 256, 256>>>(Wv, pWhi + (long)(NH_ + NKV_) * HD_ * HID_,
                                            pWlo + (long)(NH_ + NKV_) * HD_ * HID_, n4);
    n4 = HID_ * HID_ / 4;
    split_kernel<<<(n4 + 255) / 256, 256>>>(Wo, pWOhi, pWOlo, n4);

    // 2) QKV projection (tensor cores, 2-pass: Ah*(Wh+Wl)) + scatter
    hgemm<1, 2><<<dim3(NQKV / BN, MTOK / BM), 256, HGEMM_SMEM>>>(
        pAhi, pAlo, pWhi, pWlo, nullptr, MTOK, NQKV, HID_);

    // 3) RoPE + fp16 conversion of Q (hi), K (split), V (split)
    int total = QPAIRS + 2 * KPAIRS;
    rope_conv_kernel<<<(total + 255) / 256, 256>>>(cosb, sinb);

    // 4) Tensor-core causal flash attention (2-pass QK and PV)
    attn_mma_kernel<<<dim3(S_ / 128, B_ * NH_), 256, ATT_SMEM>>>();

    // 5) Output projection (tensor cores, 1-pass: Ohi*WOhi)
    hgemm<0, 1><<<dim3(HID_ / BN, MTOK / BM), 256, HGEMM_SMEM>>>(
        pOhi, pWOlo /*unused*/, pWOhi, pWOlo /*unused*/, out, MTOK, HID_, HID_);
}